// round 12
// baseline (speedup 1.0000x reference)
#include <cuda_runtime.h>
#include <cuda_bf16.h>
#include <math.h>
#include <stdint.h>

#define T_TOK   2048
#define H_DIM   1024
#define I_DIM   512
#define N_EXP   32
#define TOP_K   4
#define N_GROUP 4
#define GRP_SZ  8
#define SCALE   2.5f
#define SH_I    1024
#define MAXMB   96
#define KTW     2048            // words per (128 x 16k) A-fragment tile
#define RS      20              // raw B row stride (words), conflict-free

// 3-stage ring, BK=32 (2 ktiles per stage)
#define STAGES  3
#define STW     9216            // stage words: A 2*2048 + B 2*2560
#define SMEM_BYTES (STAGES * STW * 4)   // 110592 -> 2 CTAs = 216 KB <= 228 KB

#define RT_SMEM (1024 * 33 * 4)         // router transposed-weight smem

// ---------------- scratch ----------------------------------------------------
__device__ uint32_t g_Xsh [(size_t)16 * 64 * KTW];     // shared X A-frags (tf32)
__device__ uint32_t g_Xrt [(size_t)MAXMB * 64 * KTW];  // routed gathered X A-frags
__device__ uint32_t g_Hf  [(size_t)MAXMB * 32 * KTW];  // routed hidden A-frags
__device__ uint32_t g_Hsf [(size_t)16 * 64 * KTW];     // shared hidden A-frags

__device__ int   g_counts[N_EXP];
__device__ int   g_tok[N_EXP * T_TOK];
__device__ float g_wt[N_EXP * T_TOK];
__device__ int   g_nmb;
__device__ int   g_sched_e[MAXMB];
__device__ int   g_sched_m[MAXMB];

// ---------------- helpers ----------------------------------------------------
__device__ __forceinline__ uint32_t f2tf(float x) {
    uint32_t r; asm("cvt.rna.tf32.f32 %0, %1;" : "=r"(r) : "f"(x)); return r;
}
__device__ __forceinline__ uint32_t w2tf(uint32_t w) { return f2tf(__uint_as_float(w)); }
__device__ __forceinline__ void mma8(float* c, const uint32_t* a, uint32_t b0, uint32_t b1) {
    asm volatile("mma.sync.aligned.m16n8k8.row.col.f32.tf32.tf32.f32 "
        "{%0,%1,%2,%3}, {%4,%5,%6,%7}, {%8,%9}, {%0,%1,%2,%3};\n"
        : "+f"(c[0]), "+f"(c[1]), "+f"(c[2]), "+f"(c[3])
        : "r"(a[0]), "r"(a[1]), "r"(a[2]), "r"(a[3]), "r"(b0), "r"(b1));
}
__device__ __forceinline__ uint32_t smem_u32(const void* p) {
    uint32_t a;
    asm("{ .reg .u64 t; cvta.to.shared.u64 t, %1; cvt.u32.u64 %0, t; }" : "=r"(a) : "l"(p));
    return a;
}
__device__ __forceinline__ void cpa16(uint32_t dst, const void* src) {
    asm volatile("cp.async.cg.shared.global [%0], [%1], 16;" :: "r"(dst), "l"(src));
}
#define CPA_COMMIT() asm volatile("cp.async.commit_group;" ::: "memory")
#define CPA_WAIT1()  asm volatile("cp.async.wait_group 1;"  ::: "memory")
#define CPA_WAIT0()  asm volatile("cp.async.wait_group 0;"  ::: "memory")

// fragment addressing (validated R4-R11)
__device__ __forceinline__ int fragA_word(int r, int k) {
    int lt = r >> 4, lg = r & 7, lh = (r >> 3) & 1;
    int ks = k >> 3, k4 = (k >> 2) & 1, kl = k & 3;
    int x = (lg & 3) ^ (ks << 1);
    return lt * 256 + ks * 128 + lg * 16 + ((kl ^ x) << 2) + lh + 2 * k4;
}
__device__ __forceinline__ uint4 ldA_frag(const uint32_t* buf, int t, int ks, int gid, int tig) {
    int x = (gid & 3) ^ (ks << 1);
    return *(const uint4*)&buf[t * 256 + ks * 128 + gid * 16 + ((tig ^ x) << 2)];
}

// ---------------------------------------------------------------------------
// Router (validated R10: transposed weights in smem).
__global__ __launch_bounds__(512)
void router_kernel(const float* __restrict__ hs,
                   const float* __restrict__ rw,
                   const float* __restrict__ rb) {
    extern __shared__ float sWT[];   // [1024][33]
    int tid = threadIdx.x;
    for (int i = tid; i < N_EXP * H_DIM; i += 512) {
        int e = i >> 10, h = i & 1023;
        sWT[h * 33 + e] = rw[i];
    }
    __syncthreads();

    int warp = tid >> 5, lane = tid & 31;
    int t = blockIdx.x * 16 + warp;
    const float* x = hs + (size_t)t * H_DIM;

    float a0 = 0.f, a1 = 0.f, a2 = 0.f, a3 = 0.f;
    #pragma unroll 4
    for (int h = 0; h < H_DIM; h += 4) {
        float4 xv = *(const float4*)(x + h);
        a0 = fmaf(xv.x, sWT[(h + 0) * 33 + lane], a0);
        a1 = fmaf(xv.y, sWT[(h + 1) * 33 + lane], a1);
        a2 = fmaf(xv.z, sWT[(h + 2) * 33 + lane], a2);
        a3 = fmaf(xv.w, sWT[(h + 3) * 33 + lane], a3);
    }
    float logit = (a0 + a1) + (a2 + a3);
    float score = 1.f / (1.f + expf(-logit));
    float sfc   = score + rb[lane];

    float s[N_EXP], sc[N_EXP];
    #pragma unroll
    for (int e = 0; e < N_EXP; e++) {
        s[e]  = __shfl_sync(0xffffffffu, sfc, e);
        sc[e] = __shfl_sync(0xffffffffu, score, e);
    }

    if (lane == 0) {
        float gsc[N_GROUP];
        #pragma unroll
        for (int g = 0; g < N_GROUP; g++) {
            float m1 = -1e30f, m2 = -1e30f;
            #pragma unroll
            for (int j = 0; j < GRP_SZ; j++) {
                float v = s[g * GRP_SZ + j];
                if (v > m1) { m2 = m1; m1 = v; }
                else if (v > m2) { m2 = v; }
            }
            gsc[g] = m1 + m2;
        }
        int g1 = 0;
        #pragma unroll
        for (int g = 1; g < N_GROUP; g++) if (gsc[g] > gsc[g1]) g1 = g;
        int g2 = -1;
        #pragma unroll
        for (int g = 0; g < N_GROUP; g++) {
            if (g == g1) continue;
            if (g2 < 0 || gsc[g] > gsc[g2]) g2 = g;
        }
        float v[N_EXP];
        #pragma unroll
        for (int e = 0; e < N_EXP; e++) {
            int g = e / GRP_SZ;
            v[e] = (g == g1 || g == g2) ? s[e] : -1e30f;
        }
        int   idx[TOP_K];
        float wsum = 0.f;
        #pragma unroll
        for (int k = 0; k < TOP_K; k++) {
            int b = 0;
            #pragma unroll
            for (int e = 1; e < N_EXP; e++) if (v[e] > v[b]) b = e;
            idx[k] = b;
            v[b] = -2e30f;
            wsum += sc[b];
        }
        float inv = SCALE / (wsum + 1e-20f);
        #pragma unroll
        for (int k = 0; k < TOP_K; k++) {
            int e = idx[k];
            int p = atomicAdd(&g_counts[e], 1);
            g_tok[e * T_TOK + p] = t;
            g_wt [e * T_TOK + p] = sc[e] * inv;
        }
    }
}

__global__ void sched_kernel() {
    int lane = threadIdx.x;
    int cnt = (lane < N_EXP) ? g_counts[lane] : 0;
    int nb = (cnt + 127) >> 7;
    int incl = nb;
    #pragma unroll
    for (int off = 1; off < 32; off <<= 1) {
        int v = __shfl_up_sync(0xffffffffu, incl, off);
        if (lane >= off) incl += v;
    }
    int base = incl - nb;
    for (int j = 0; j < nb; j++) {
        g_sched_e[base + j] = lane;
        g_sched_m[base + j] = j * 128;
    }
    if (lane == 31) g_nmb = incl;
}

// ---------------------------------------------------------------------------
// A-side prep (tf32 + fragment relayout; X reused 8-16x downstream).
__device__ __forceinline__ void prepA_rowtile(uint32_t* dst, const float* src,
                                              int r, int h8, int kt0, int nkt) {
    for (int kt = kt0; kt < kt0 + nkt; kt++) {
        const float* s = src + kt * 16 + h8;
        float4 v0 = *(const float4*)s, v1 = *(const float4*)(s + 4);
        uint32_t* d = dst + (size_t)kt * KTW;
        float f[8] = {v0.x, v0.y, v0.z, v0.w, v1.x, v1.y, v1.z, v1.w};
        #pragma unroll
        for (int i = 0; i < 8; i++) d[fragA_word(r, h8 + i)] = f2tf(f[i]);
    }
}
__global__ void prep_X(const float* __restrict__ X) {
    int bid = blockIdx.x, ktg = blockIdx.y;
    int r = threadIdx.x >> 1, h8 = (threadIdx.x & 1) * 8;
    if (bid < 16) {
        prepA_rowtile(g_Xsh + (size_t)bid * 64 * KTW,
                      X + (size_t)(bid * 128 + r) * H_DIM, r, h8, ktg * 8, 8);
    } else {
        int mb = bid - 16;
        if (mb >= g_nmb) return;
        int e = g_sched_e[mb], m0 = g_sched_m[mb], cnt = g_counts[e];
        int ar = m0 + r; if (ar >= cnt) ar = cnt - 1;
        int tok = g_tok[e * T_TOK + ar];
        prepA_rowtile(g_Xrt + (size_t)mb * 64 * KTW,
                      X + (size_t)tok * H_DIM, r, h8, ktg * 8, 8);
    }
}

// ---------------------------------------------------------------------------
// gateup: CTA 128 rows x 64 i-cols, G/U interleaved B rows (validated R11).
// 8 warps (2m x 4n), warp 64x32. 3-stage BK=32 cp.async ring.
__global__ __launch_bounds__(256, 2)
void gateup_all(const float* __restrict__ GW, const float* __restrict__ UW,
                const float* __restrict__ SGW, const float* __restrict__ SUW) {
    extern __shared__ uint32_t dsm[];
    uint32_t sb = smem_u32(dsm);
    int bid = blockIdx.x;

    const uint32_t* Ag;
    const float *gRowBase, *uRowBase;
    uint32_t* Hdst;
    int rows_valid, ktbase;
    if (bid < 256) {
        int mt = bid >> 4, i64 = bid & 15;
        Ag = g_Xsh + (size_t)mt * 64 * KTW;
        gRowBase = SGW + (size_t)(i64 * 64) * H_DIM;
        uRowBase = SUW + (size_t)(i64 * 64) * H_DIM;
        Hdst = g_Hsf + (size_t)mt * 64 * KTW;
        rows_valid = 128; ktbase = i64 * 4;
    } else {
        int rb = bid - 256, mb = rb >> 3;
        if (mb >= g_nmb) return;
        int e = g_sched_e[mb], m0 = g_sched_m[mb], cnt = g_counts[e];
        int i64 = rb & 7;
        Ag = g_Xrt + (size_t)mb * 64 * KTW;
        gRowBase = GW + ((size_t)e * I_DIM + i64 * 64) * H_DIM;
        uRowBase = UW + ((size_t)e * I_DIM + i64 * 64) * H_DIM;
        Hdst = g_Hf + (size_t)mb * 32 * KTW;
        rows_valid = min(128, cnt - m0); ktbase = i64 * 4;
    }

    int tid = threadIdx.x, lane = tid & 31, wid = tid >> 5;
    int gid = lane >> 2, tig = lane & 3;
    int wm = (wid & 1) * 64;
    int wn = (wid >> 1) * 32;

    // B loader: smem row bc <- G/U weight row per 8-row interleave
    int bc = tid >> 1, bh = (tid & 1) * 8;
    int grp = bc >> 4, wi = bc & 15;
    const float* bRow = ((wi >= 8) ? uRowBase : gRowBase)
                        + (size_t)(grp * 8 + (wi & 7)) * H_DIM + bh;

    // stage st holds ktiles (2j, 2j+1)
    auto copy_stage = [&](int st, int j) {
        #pragma unroll
        for (int kt = 0; kt < 2; kt++) {
            int kidx = 2 * j + kt;
            uint32_t dA = sb + (uint32_t)(st * STW + kt * 2048 + tid * 8) * 4;
            const uint32_t* sA = Ag + (size_t)kidx * KTW + tid * 8;
            cpa16(dA, sA); cpa16(dA + 16, sA + 4);
            uint32_t dB = sb + (uint32_t)(st * STW + 4096 + kt * 2560 + bc * RS + bh) * 4;
            const float* sB = bRow + kidx * 16;
            cpa16(dB, sB); cpa16(dB + 16, sB + 4);
        }
    };

    copy_stage(0, 0); CPA_COMMIT();
    copy_stage(1, 1); CPA_COMMIT();

    float acc[4][4][4] = {{{0}}};

    const int NOUT = H_DIM / 32;   // 32
    for (int it = 0; it < NOUT; it++) {
        CPA_WAIT1();
        __syncthreads();
        int st = it % 3;
        #pragma unroll
        for (int kt = 0; kt < 2; kt++) {
            const uint32_t* As = dsm + st * STW + kt * 2048;
            const uint32_t* Bs = dsm + st * STW + 4096 + kt * 2560;

            uint32_t a[4][2][4];
            #pragma unroll
            for (int mt = 0; mt < 4; mt++) {
                int t = (wid & 1) * 4 + mt;
                #pragma unroll
                for (int ks = 0; ks < 2; ks++) {
                    uint4 av = ldA_frag(As, t, ks, gid, tig);
                    a[mt][ks][0] = av.x; a[mt][ks][1] = av.y;
                    a[mt][ks][2] = av.z; a[mt][ks][3] = av.w;
                }
            }
            #pragma unroll
            for (int nt = 0; nt < 4; nt++) {
                int c = wn + nt * 8 + gid;
                #pragma unroll
                for (int ks = 0; ks < 2; ks++) {
                    int cb = c * RS + ks * 8 + tig;
                    uint32_t b0 = w2tf(Bs[cb]), b1 = w2tf(Bs[cb + 4]);
                    #pragma unroll
                    for (int mt = 0; mt < 4; mt++)
                        mma8(acc[mt][nt], a[mt][ks], b0, b1);
                }
            }
        }
        if (it + 2 < NOUT) copy_stage((it + 2) % 3, it + 2);
        CPA_COMMIT();
    }
    CPA_WAIT0();

    // warp-local epilogue: nt pairs (0,1),(2,3) = (G,U) on same i-cols
    #pragma unroll
    for (int mt = 0; mt < 4; mt++) {
        #pragma unroll
        for (int half = 0; half < 2; half++) {
            int r = wm + mt * 16 + gid + half * 8;
            if (r >= rows_valid) continue;
            #pragma unroll
            for (int p = 0; p < 2; p++) {
                int icol0 = (wn >> 1) + p * 8 + 2 * tig;
                #pragma unroll
                for (int j = 0; j < 2; j++) {
                    float g = acc[mt][2 * p    ][half * 2 + j];
                    float u = acc[mt][2 * p + 1][half * 2 + j];
                    float h = (g / (1.f + expf(-g))) * u;
                    int icol = icol0 + j;
                    Hdst[(size_t)(ktbase + (icol >> 4)) * KTW + fragA_word(r, icol & 15)] = f2tf(h);
                }
            }
        }
    }
}

// ---------------------------------------------------------------------------
// down: CTA 128 x 128, 8 warps (2m x 4n), warp 64x32, 3-stage BK=32 ring.
__global__ __launch_bounds__(256, 2)
void down_all(const float* __restrict__ DW, const float* __restrict__ SDW,
              float* __restrict__ out) {
    extern __shared__ uint32_t dsm[];
    uint32_t sb = smem_u32(dsm);
    int bid = blockIdx.x;

    const uint32_t* Ag;
    const float* bRowBase;
    int NOUT, n0, cnt = 0, m0 = 0, e = 0, bK;
    bool routed;
    if (bid < 128) {
        int mt = bid >> 3, nt = bid & 7;
        Ag = g_Hsf + (size_t)mt * 64 * KTW;
        bRowBase = SDW + (size_t)(nt * 128) * SH_I;
        NOUT = SH_I / 32; n0 = nt * 128; m0 = mt * 128; bK = SH_I; routed = false;
    } else {
        int rb = bid - 128, mb = rb >> 3;
        if (mb >= g_nmb) return;
        e = g_sched_e[mb]; m0 = g_sched_m[mb]; cnt = g_counts[e];
        int nt = rb & 7;
        Ag = g_Hf + (size_t)mb * 32 * KTW;
        bRowBase = DW + ((size_t)e * H_DIM + nt * 128) * I_DIM;
        NOUT = I_DIM / 32; n0 = nt * 128; bK = I_DIM; routed = true;
    }

    int tid = threadIdx.x, lane = tid & 31, wid = tid >> 5;
    int gid = lane >> 2, tig = lane & 3;
    int wm = (wid & 1) * 64;
    int wn = (wid >> 1) * 32;

    int bc = tid >> 1, bh = (tid & 1) * 8;
    const float* bRow = bRowBase + (size_t)bc * bK + bh;

    auto copy_stage = [&](int st, int j) {
        #pragma unroll
        for (int kt = 0; kt < 2; kt++) {
            int kidx = 2 * j + kt;
            uint32_t dA = sb + (uint32_t)(st * STW + kt * 2048 + tid * 8) * 4;
            const uint32_t* sA = Ag + (size_t)kidx * KTW + tid * 8;
            cpa16(dA, sA); cpa16(dA + 16, sA + 4);
            uint32_t dB = sb + (uint32_t)(st * STW + 4096 + kt * 2560 + bc * RS + bh) * 4;
            const float* sB = bRow + kidx * 16;
            cpa16(dB, sB); cpa16(dB + 16, sB + 4);
        }
    };

    copy_stage(0, 0); CPA_COMMIT();
    copy_stage(1, 1); CPA_COMMIT();

    float acc[4][4][4] = {{{0}}};

    for (int it = 0; it < NOUT; it++) {
        CPA_WAIT1();
        __syncthreads();
        int st = it % 3;
        #pragma unroll
        for (int kt = 0; kt < 2; kt++) {
            const uint32_t* As = dsm + st * STW + kt * 2048;
            const uint32_t* Bs = dsm + st * STW + 4096 + kt * 2560;

            uint32_t a[4][2][4];
            #pragma unroll
            for (int mt = 0; mt < 4; mt++) {
                int t = (wid & 1) * 4 + mt;
                #pragma unroll
                for (int ks = 0; ks < 2; ks++) {
                    uint4 av = ldA_frag(As, t, ks, gid, tig);
                    a[mt][ks][0] = av.x; a[mt][ks][1] = av.y;
                    a[mt][ks][2] = av.z; a[mt][ks][3] = av.w;
                }
            }
            #pragma unroll
            for (int nt = 0; nt < 4; nt++) {
                int c = wn + nt * 8 + gid;
                #pragma unroll
                for (int ks = 0; ks < 2; ks++) {
                    int cb = c * RS + ks * 8 + tig;
                    uint32_t b0 = w2tf(Bs[cb]), b1 = w2tf(Bs[cb + 4]);
                    #pragma unroll
                    for (int mt = 0; mt < 4; mt++)
                        mma8(acc[mt][nt], a[mt][ks], b0, b1);
                }
            }
        }
        if (it + 2 < NOUT) copy_stage((it + 2) % 3, it + 2);
        CPA_COMMIT();
    }
    CPA_WAIT0();

    #pragma unroll
    for (int mt = 0; mt < 4; mt++) {
        #pragma unroll
        for (int half = 0; half < 2; half++) {
            int r = wm + mt * 16 + gid + half * 8;
            float wt = 1.f;
            float* op;
            if (routed) {
                if (m0 + r >= cnt) continue;
                int tok = g_tok[e * T_TOK + m0 + r];
                wt = g_wt[e * T_TOK + m0 + r];
                op = out + (size_t)tok * H_DIM;
            } else {
                op = out + (size_t)(m0 + r) * H_DIM;
            }
            #pragma unroll
            for (int nt = 0; nt < 4; nt++) {
                int cb = n0 + wn + nt * 8 + 2 * tig;
                atomicAdd(&op[cb],     acc[mt][nt][half * 2]     * wt);
                atomicAdd(&op[cb + 1], acc[mt][nt][half * 2 + 1] * wt);
            }
        }
    }
}

// ---------------------------------------------------------------------------
extern "C" void kernel_launch(void* const* d_in, const int* in_sizes, int n_in,
                              void* d_out, int out_size) {
    const float* hs  = (const float*)d_in[0];
    const float* rw  = (const float*)d_in[1];
    const float* rb  = (const float*)d_in[2];
    const float* gw  = (const float*)d_in[3];
    const float* uw  = (const float*)d_in[4];
    const float* dw  = (const float*)d_in[5];
    const float* sgw = (const float*)d_in[6];
    const float* suw = (const float*)d_in[7];
    const float* sdw = (const float*)d_in[8];
    float* out = (float*)d_out;

    cudaFuncSetAttribute(router_kernel, cudaFuncAttributeMaxDynamicSharedMemorySize, RT_SMEM);
    cudaFuncSetAttribute(gateup_all, cudaFuncAttributeMaxDynamicSharedMemorySize, SMEM_BYTES);
    cudaFuncSetAttribute(down_all,   cudaFuncAttributeMaxDynamicSharedMemorySize, SMEM_BYTES);

    void* cnt_ptr = nullptr;
    cudaGetSymbolAddress(&cnt_ptr, g_counts);
    cudaMemsetAsync(cnt_ptr, 0, N_EXP * sizeof(int));
    cudaMemsetAsync(out, 0, (size_t)T_TOK * H_DIM * sizeof(float));

    router_kernel<<<T_TOK / 16, 512, RT_SMEM>>>(hs, rw, rb);   // launch 1
    sched_kernel<<<1, 32>>>();                                  // launch 2
    prep_X<<<dim3(16 + MAXMB, 8), 256>>>(hs);                   // launch 3
    gateup_all<<<256 + 8 * MAXMB, 256, SMEM_BYTES>>>(gw, uw, sgw, suw);  // launch 4 (profiled)
    down_all  <<<128 + 8 * MAXMB, 256, SMEM_BYTES>>>(dw, sdw, out);      // launch 5
}

// round 14
// speedup vs baseline: 1.6360x; 1.6360x over previous
#include <cuda_runtime.h>
#include <cuda_bf16.h>
#include <math.h>
#include <stdint.h>

#define T_TOK   2048
#define H_DIM   1024
#define I_DIM   512
#define N_EXP   32
#define TOP_K   4
#define N_GROUP 4
#define GRP_SZ  8
#define SCALE   2.5f
#define SH_I    1024
#define MAXMB   96
#define KTW     2048            // words per (128 x 16k) A-fragment tile
#define RS      20              // raw B row stride (words), conflict-free

// R11 validated operating point: 4-stage ring, BK=16
#define STAGES  4
#define STW     4608            // stage words: A 2048 + B 2560
#define SMEM_BYTES (STAGES * STW * 4)   // 73728

#define RT_SMEM (1024 * 33 * 4)         // router transposed-weight smem

// ---------------- scratch ----------------------------------------------------
__device__ uint32_t g_Xsh [(size_t)16 * 64 * KTW];     // shared X A-frags (tf32)
__device__ uint32_t g_Xrt [(size_t)MAXMB * 64 * KTW];  // routed gathered X A-frags
__device__ uint32_t g_Hf  [(size_t)MAXMB * 32 * KTW];  // routed hidden A-frags
__device__ uint32_t g_Hsf [(size_t)16 * 64 * KTW];     // shared hidden A-frags

__device__ int   g_counts[N_EXP];
__device__ int   g_tok[N_EXP * T_TOK];
__device__ float g_wt[N_EXP * T_TOK];
__device__ int   g_nmb;
__device__ int   g_sched_e[MAXMB];
__device__ int   g_sched_m[MAXMB];

// ---------------- helpers ----------------------------------------------------
__device__ __forceinline__ uint32_t f2tf(float x) {
    uint32_t r; asm("cvt.rna.tf32.f32 %0, %1;" : "=r"(r) : "f"(x)); return r;
}
__device__ __forceinline__ uint32_t w2tf(uint32_t w) { return f2tf(__uint_as_float(w)); }
__device__ __forceinline__ void mma8(float* c, const uint32_t* a, uint32_t b0, uint32_t b1) {
    asm volatile("mma.sync.aligned.m16n8k8.row.col.f32.tf32.tf32.f32 "
        "{%0,%1,%2,%3}, {%4,%5,%6,%7}, {%8,%9}, {%0,%1,%2,%3};\n"
        : "+f"(c[0]), "+f"(c[1]), "+f"(c[2]), "+f"(c[3])
        : "r"(a[0]), "r"(a[1]), "r"(a[2]), "r"(a[3]), "r"(b0), "r"(b1));
}
__device__ __forceinline__ uint32_t smem_u32(const void* p) {
    uint32_t a;
    asm("{ .reg .u64 t; cvta.to.shared.u64 t, %1; cvt.u32.u64 %0, t; }" : "=r"(a) : "l"(p));
    return a;
}
__device__ __forceinline__ void cpa16(uint32_t dst, const void* src) {
    asm volatile("cp.async.cg.shared.global [%0], [%1], 16;" :: "r"(dst), "l"(src));
}
#define CPA_COMMIT() asm volatile("cp.async.commit_group;" ::: "memory")
#define CPA_WAIT2()  asm volatile("cp.async.wait_group 2;"  ::: "memory")
#define CPA_WAIT0()  asm volatile("cp.async.wait_group 0;"  ::: "memory")

// fragment addressing (validated R4-R12)
__device__ __forceinline__ int fragA_word(int r, int k) {
    int lt = r >> 4, lg = r & 7, lh = (r >> 3) & 1;
    int ks = k >> 3, k4 = (k >> 2) & 1, kl = k & 3;
    int x = (lg & 3) ^ (ks << 1);
    return lt * 256 + ks * 128 + lg * 16 + ((kl ^ x) << 2) + lh + 2 * k4;
}
__device__ __forceinline__ uint4 ldA_frag(const uint32_t* buf, int t, int ks, int gid, int tig) {
    int x = (gid & 3) ^ (ks << 1);
    return *(const uint4*)&buf[t * 256 + ks * 128 + gid * 16 + ((tig ^ x) << 2)];
}

// ---------------------------------------------------------------------------
// Router (validated R10: transposed weights in smem).
__global__ __launch_bounds__(512)
void router_kernel(const float* __restrict__ hs,
                   const float* __restrict__ rw,
                   const float* __restrict__ rb) {
    extern __shared__ float sWT[];   // [1024][33]
    int tid = threadIdx.x;
    for (int i = tid; i < N_EXP * H_DIM; i += 512) {
        int e = i >> 10, h = i & 1023;
        sWT[h * 33 + e] = rw[i];
    }
    __syncthreads();

    int warp = tid >> 5, lane = tid & 31;
    int t = blockIdx.x * 16 + warp;
    const float* x = hs + (size_t)t * H_DIM;

    float a0 = 0.f, a1 = 0.f, a2 = 0.f, a3 = 0.f;
    #pragma unroll 4
    for (int h = 0; h < H_DIM; h += 4) {
        float4 xv = *(const float4*)(x + h);
        a0 = fmaf(xv.x, sWT[(h + 0) * 33 + lane], a0);
        a1 = fmaf(xv.y, sWT[(h + 1) * 33 + lane], a1);
        a2 = fmaf(xv.z, sWT[(h + 2) * 33 + lane], a2);
        a3 = fmaf(xv.w, sWT[(h + 3) * 33 + lane], a3);
    }
    float logit = (a0 + a1) + (a2 + a3);
    float score = 1.f / (1.f + expf(-logit));
    float sfc   = score + rb[lane];

    float s[N_EXP], sc[N_EXP];
    #pragma unroll
    for (int e = 0; e < N_EXP; e++) {
        s[e]  = __shfl_sync(0xffffffffu, sfc, e);
        sc[e] = __shfl_sync(0xffffffffu, score, e);
    }

    if (lane == 0) {
        float gsc[N_GROUP];
        #pragma unroll
        for (int g = 0; g < N_GROUP; g++) {
            float m1 = -1e30f, m2 = -1e30f;
            #pragma unroll
            for (int j = 0; j < GRP_SZ; j++) {
                float v = s[g * GRP_SZ + j];
                if (v > m1) { m2 = m1; m1 = v; }
                else if (v > m2) { m2 = v; }
            }
            gsc[g] = m1 + m2;
        }
        int g1 = 0;
        #pragma unroll
        for (int g = 1; g < N_GROUP; g++) if (gsc[g] > gsc[g1]) g1 = g;
        int g2 = -1;
        #pragma unroll
        for (int g = 0; g < N_GROUP; g++) {
            if (g == g1) continue;
            if (g2 < 0 || gsc[g] > gsc[g2]) g2 = g;
        }
        float v[N_EXP];
        #pragma unroll
        for (int e = 0; e < N_EXP; e++) {
            int g = e / GRP_SZ;
            v[e] = (g == g1 || g == g2) ? s[e] : -1e30f;
        }
        int   idx[TOP_K];
        float wsum = 0.f;
        #pragma unroll
        for (int k = 0; k < TOP_K; k++) {
            int b = 0;
            #pragma unroll
            for (int e = 1; e < N_EXP; e++) if (v[e] > v[b]) b = e;
            idx[k] = b;
            v[b] = -2e30f;
            wsum += sc[b];
        }
        float inv = SCALE / (wsum + 1e-20f);
        #pragma unroll
        for (int k = 0; k < TOP_K; k++) {
            int e = idx[k];
            int p = atomicAdd(&g_counts[e], 1);
            g_tok[e * T_TOK + p] = t;
            g_wt [e * T_TOK + p] = sc[e] * inv;
        }
    }
}

__global__ void sched_kernel() {
    int lane = threadIdx.x;
    int cnt = (lane < N_EXP) ? g_counts[lane] : 0;
    int nb = (cnt + 127) >> 7;
    int incl = nb;
    #pragma unroll
    for (int off = 1; off < 32; off <<= 1) {
        int v = __shfl_up_sync(0xffffffffu, incl, off);
        if (lane >= off) incl += v;
    }
    int base = incl - nb;
    for (int j = 0; j < nb; j++) {
        g_sched_e[base + j] = lane;
        g_sched_m[base + j] = j * 128;
    }
    if (lane == 31) g_nmb = incl;
}

// ---------------------------------------------------------------------------
// A-side prep (tf32 + fragment relayout; X reused 8-16x downstream).
__device__ __forceinline__ void prepA_rowtile(uint32_t* dst, const float* src,
                                              int r, int h8, int kt0, int nkt) {
    for (int kt = kt0; kt < kt0 + nkt; kt++) {
        const float* s = src + kt * 16 + h8;
        float4 v0 = *(const float4*)s, v1 = *(const float4*)(s + 4);
        uint32_t* d = dst + (size_t)kt * KTW;
        float f[8] = {v0.x, v0.y, v0.z, v0.w, v1.x, v1.y, v1.z, v1.w};
        #pragma unroll
        for (int i = 0; i < 8; i++) d[fragA_word(r, h8 + i)] = f2tf(f[i]);
    }
}
__global__ void prep_Xsh(const float* __restrict__ X) {
    int bid = blockIdx.x, ktg = blockIdx.y;
    int r = threadIdx.x >> 1, h8 = (threadIdx.x & 1) * 8;
    prepA_rowtile(g_Xsh + (size_t)bid * 64 * KTW,
                  X + (size_t)(bid * 128 + r) * H_DIM, r, h8, ktg * 8, 8);
}
__global__ void prep_Xrt(const float* __restrict__ X) {
    int mb = blockIdx.x, ktg = blockIdx.y;
    if (mb >= g_nmb) return;
    int e = g_sched_e[mb], m0 = g_sched_m[mb], cnt = g_counts[e];
    int r = threadIdx.x >> 1, h8 = (threadIdx.x & 1) * 8;
    int ar = m0 + r; if (ar >= cnt) ar = cnt - 1;
    int tok = g_tok[e * T_TOK + ar];
    prepA_rowtile(g_Xrt + (size_t)mb * 64 * KTW,
                  X + (size_t)tok * H_DIM, r, h8, ktg * 8, 8);
}

// ---------------------------------------------------------------------------
// gateup (R11 body): CTA 128 rows x 64 i-cols, G/U interleaved B rows.
// 8 warps (2m x 4n), warp 64x32, 4-stage BK=16 ring. mode: 0=shared, 1=routed.
__global__ __launch_bounds__(256, 2)
void gateup_k(int mode,
              const float* __restrict__ GW, const float* __restrict__ UW,
              const float* __restrict__ SGW, const float* __restrict__ SUW) {
    extern __shared__ uint32_t dsm[];
    uint32_t sb = smem_u32(dsm);
    int bid = blockIdx.x;

    const uint32_t* Ag;
    const float *gRowBase, *uRowBase;
    uint32_t* Hdst;
    int rows_valid, ktbase;
    if (mode == 0) {
        int mt = bid >> 4, i64 = bid & 15;
        Ag = g_Xsh + (size_t)mt * 64 * KTW;
        gRowBase = SGW + (size_t)(i64 * 64) * H_DIM;
        uRowBase = SUW + (size_t)(i64 * 64) * H_DIM;
        Hdst = g_Hsf + (size_t)mt * 64 * KTW;
        rows_valid = 128; ktbase = i64 * 4;
    } else {
        int mb = bid >> 3;
        if (mb >= g_nmb) return;
        int e = g_sched_e[mb], m0 = g_sched_m[mb], cnt = g_counts[e];
        int i64 = bid & 7;
        Ag = g_Xrt + (size_t)mb * 64 * KTW;
        gRowBase = GW + ((size_t)e * I_DIM + i64 * 64) * H_DIM;
        uRowBase = UW + ((size_t)e * I_DIM + i64 * 64) * H_DIM;
        Hdst = g_Hf + (size_t)mb * 32 * KTW;
        rows_valid = min(128, cnt - m0); ktbase = i64 * 4;
    }

    int tid = threadIdx.x, lane = tid & 31, wid = tid >> 5;
    int gid = lane >> 2, tig = lane & 3;
    int wm = (wid & 1) * 64;
    int wn = (wid >> 1) * 32;

    // B loader: smem row bc <- G/U weight row per 8-row interleave
    int bc = tid >> 1, bh = (tid & 1) * 8;
    int grp = bc >> 4, wi = bc & 15;
    const float* bRow = ((wi >= 8) ? uRowBase : gRowBase)
                        + (size_t)(grp * 8 + (wi & 7)) * H_DIM + bh;

    auto copy_stage = [&](int st, int j) {
        uint32_t dA = sb + (uint32_t)(st * STW + tid * 8) * 4;
        const uint32_t* sA = Ag + (size_t)j * KTW + tid * 8;
        cpa16(dA, sA); cpa16(dA + 16, sA + 4);
        uint32_t dB = sb + (uint32_t)(st * STW + 2048 + bc * RS + bh) * 4;
        const float* sB = bRow + j * 16;
        cpa16(dB, sB); cpa16(dB + 16, sB + 4);
    };

    copy_stage(0, 0); CPA_COMMIT();
    copy_stage(1, 1); CPA_COMMIT();
    copy_stage(2, 2); CPA_COMMIT();

    float acc[4][4][4] = {{{0}}};

    const int NIT = H_DIM / 16;   // 64
    for (int it = 0; it < NIT; it++) {
        CPA_WAIT2();
        __syncthreads();
        int st = it & 3;
        const uint32_t* As = dsm + st * STW;
        const uint32_t* Bs = dsm + st * STW + 2048;

        uint32_t a[4][2][4];
        #pragma unroll
        for (int mt = 0; mt < 4; mt++) {
            int t = (wid & 1) * 4 + mt;
            #pragma unroll
            for (int ks = 0; ks < 2; ks++) {
                uint4 av = ldA_frag(As, t, ks, gid, tig);
                a[mt][ks][0] = av.x; a[mt][ks][1] = av.y;
                a[mt][ks][2] = av.z; a[mt][ks][3] = av.w;
            }
        }
        #pragma unroll
        for (int nt = 0; nt < 4; nt++) {
            int c = wn + nt * 8 + gid;
            #pragma unroll
            for (int ks = 0; ks < 2; ks++) {
                int cb = c * RS + ks * 8 + tig;
                uint32_t b0 = w2tf(Bs[cb]), b1 = w2tf(Bs[cb + 4]);
                #pragma unroll
                for (int mt = 0; mt < 4; mt++)
                    mma8(acc[mt][nt], a[mt][ks], b0, b1);
            }
        }
        if (it + 3 < NIT) copy_stage((it + 3) & 3, it + 3);
        CPA_COMMIT();
    }
    CPA_WAIT0();

    // warp-local epilogue: nt pairs (0,1),(2,3) = (G,U) on same i-cols
    #pragma unroll
    for (int mt = 0; mt < 4; mt++) {
        #pragma unroll
        for (int half = 0; half < 2; half++) {
            int r = wm + mt * 16 + gid + half * 8;
            if (r >= rows_valid) continue;
            #pragma unroll
            for (int p = 0; p < 2; p++) {
                int icol0 = (wn >> 1) + p * 8 + 2 * tig;
                #pragma unroll
                for (int j = 0; j < 2; j++) {
                    float g = acc[mt][2 * p    ][half * 2 + j];
                    float u = acc[mt][2 * p + 1][half * 2 + j];
                    float h = (g / (1.f + expf(-g))) * u;
                    int icol = icol0 + j;
                    Hdst[(size_t)(ktbase + (icol >> 4)) * KTW + fragA_word(r, icol & 15)] = f2tf(h);
                }
            }
        }
    }
}

// ---------------------------------------------------------------------------
// down (R11 body): CTA 128 x 128, 8 warps (2m x 4n), warp 64x32, 4-stage ring.
__global__ __launch_bounds__(256, 2)
void down_k(int mode, const float* __restrict__ DW, const float* __restrict__ SDW,
            float* __restrict__ out) {
    extern __shared__ uint32_t dsm[];
    uint32_t sb = smem_u32(dsm);
    int bid = blockIdx.x;

    const uint32_t* Ag;
    const float* bRowBase;
    int NIT, n0, cnt = 0, m0 = 0, e = 0, bK;
    if (mode == 0) {
        int mt = bid >> 3, nt = bid & 7;
        Ag = g_Hsf + (size_t)mt * 64 * KTW;
        bRowBase = SDW + (size_t)(nt * 128) * SH_I;
        NIT = 64; n0 = nt * 128; m0 = mt * 128; bK = SH_I;
    } else {
        int mb = bid >> 3;
        if (mb >= g_nmb) return;
        e = g_sched_e[mb]; m0 = g_sched_m[mb]; cnt = g_counts[e];
        int nt = bid & 7;
        Ag = g_Hf + (size_t)mb * 32 * KTW;
        bRowBase = DW + ((size_t)e * H_DIM + nt * 128) * I_DIM;
        NIT = 32; n0 = nt * 128; bK = I_DIM;
    }

    int tid = threadIdx.x, lane = tid & 31, wid = tid >> 5;
    int gid = lane >> 2, tig = lane & 3;
    int wm = (wid & 1) * 64;
    int wn = (wid >> 1) * 32;

    int bc = tid >> 1, bh = (tid & 1) * 8;
    const float* bRow = bRowBase + (size_t)bc * bK + bh;

    auto copy_stage = [&](int st, int j) {
        uint32_t dA = sb + (uint32_t)(st * STW + tid * 8) * 4;
        const uint32_t* sA = Ag + (size_t)j * KTW + tid * 8;
        cpa16(dA, sA); cpa16(dA + 16, sA + 4);
        uint32_t dB = sb + (uint32_t)(st * STW + 2048 + bc * RS + bh) * 4;
        const float* sB = bRow + j * 16;
        cpa16(dB, sB); cpa16(dB + 16, sB + 4);
    };

    copy_stage(0, 0); CPA_COMMIT();
    copy_stage(1, 1); CPA_COMMIT();
    copy_stage(2, 2); CPA_COMMIT();

    float acc[4][4][4] = {{{0}}};

    for (int it = 0; it < NIT; it++) {
        CPA_WAIT2();
        __syncthreads();
        int st = it & 3;
        const uint32_t* As = dsm + st * STW;
        const uint32_t* Bs = dsm + st * STW + 2048;

        uint32_t a[4][2][4];
        #pragma unroll
        for (int mt = 0; mt < 4; mt++) {
            int t = (wid & 1) * 4 + mt;
            #pragma unroll
            for (int ks = 0; ks < 2; ks++) {
                uint4 av = ldA_frag(As, t, ks, gid, tig);
                a[mt][ks][0] = av.x; a[mt][ks][1] = av.y;
                a[mt][ks][2] = av.z; a[mt][ks][3] = av.w;
            }
        }
        #pragma unroll
        for (int nt = 0; nt < 4; nt++) {
            int c = wn + nt * 8 + gid;
            #pragma unroll
            for (int ks = 0; ks < 2; ks++) {
                int cb = c * RS + ks * 8 + tig;
                uint32_t b0 = w2tf(Bs[cb]), b1 = w2tf(Bs[cb + 4]);
                #pragma unroll
                for (int mt = 0; mt < 4; mt++)
                    mma8(acc[mt][nt], a[mt][ks], b0, b1);
            }
        }
        if (it + 3 < NIT) copy_stage((it + 3) & 3, it + 3);
        CPA_COMMIT();
    }
    CPA_WAIT0();

    #pragma unroll
    for (int mt = 0; mt < 4; mt++) {
        #pragma unroll
        for (int half = 0; half < 2; half++) {
            int r = wm + mt * 16 + gid + half * 8;
            float wt = 1.f;
            float* op;
            if (mode == 1) {
                if (m0 + r >= cnt) continue;
                int tok = g_tok[e * T_TOK + m0 + r];
                wt = g_wt[e * T_TOK + m0 + r];
                op = out + (size_t)tok * H_DIM;
            } else {
                op = out + (size_t)(m0 + r) * H_DIM;
            }
            #pragma unroll
            for (int nt = 0; nt < 4; nt++) {
                int cb = n0 + wn + nt * 8 + 2 * tig;
                atomicAdd(&op[cb],     acc[mt][nt][half * 2]     * wt);
                atomicAdd(&op[cb + 1], acc[mt][nt][half * 2 + 1] * wt);
            }
        }
    }
}

// ---------------------------------------------------------------------------
extern "C" void kernel_launch(void* const* d_in, const int* in_sizes, int n_in,
                              void* d_out, int out_size) {
    const float* hs  = (const float*)d_in[0];
    const float* rw  = (const float*)d_in[1];
    const float* rb  = (const float*)d_in[2];
    const float* gw  = (const float*)d_in[3];
    const float* uw  = (const float*)d_in[4];
    const float* dw  = (const float*)d_in[5];
    const float* sgw = (const float*)d_in[6];
    const float* suw = (const float*)d_in[7];
    const float* sdw = (const float*)d_in[8];
    float* out = (float*)d_out;

    cudaFuncSetAttribute(router_kernel, cudaFuncAttributeMaxDynamicSharedMemorySize, RT_SMEM);
    cudaFuncSetAttribute(gateup_k, cudaFuncAttributeMaxDynamicSharedMemorySize, SMEM_BYTES);
    cudaFuncSetAttribute(down_k,   cudaFuncAttributeMaxDynamicSharedMemorySize, SMEM_BYTES);

    // one-time side stream + fork/join events (same DAG every call)
    static cudaStream_t s2 = nullptr;
    static cudaEvent_t eFork = nullptr, eJoin = nullptr;
    if (!s2) {
        cudaStreamCreateWithFlags(&s2, cudaStreamNonBlocking);
        cudaEventCreateWithFlags(&eFork, cudaEventDisableTiming);
        cudaEventCreateWithFlags(&eJoin, cudaEventDisableTiming);
    }

    void* cnt_ptr = nullptr;
    cudaGetSymbolAddress(&cnt_ptr, g_counts);
    cudaMemsetAsync(cnt_ptr, 0, N_EXP * sizeof(int));
    cudaMemsetAsync(out, 0, (size_t)T_TOK * H_DIM * sizeof(float));

    // fork: shared-expert path on s2 (independent of router)
    cudaEventRecord(eFork, 0);
    cudaStreamWaitEvent(s2, eFork, 0);
    prep_Xsh<<<dim3(16, 8), 256, 0, s2>>>(hs);
    gateup_k<<<256, 256, SMEM_BYTES, s2>>>(0, gw, uw, sgw, suw);
    down_k  <<<128, 256, SMEM_BYTES, s2>>>(0, dw, sdw, out);
    cudaEventRecord(eJoin, s2);

    // routed path on the main (capture) stream
    router_kernel<<<T_TOK / 16, 512, RT_SMEM>>>(hs, rw, rb);
    sched_kernel<<<1, 32>>>();
    prep_Xrt<<<dim3(MAXMB, 8), 256>>>(hs);
    gateup_k<<<8 * MAXMB, 256, SMEM_BYTES>>>(1, gw, uw, sgw, suw);
    down_k  <<<8 * MAXMB, 256, SMEM_BYTES>>>(1, dw, sdw, out);

    // join
    cudaStreamWaitEvent(0, eJoin, 0);
}

// round 15
// speedup vs baseline: 1.6597x; 1.0145x over previous
#include <cuda_runtime.h>
#include <cuda_bf16.h>
#include <math.h>
#include <stdint.h>

#define T_TOK   2048
#define H_DIM   1024
#define I_DIM   512
#define N_EXP   32
#define TOP_K   4
#define N_GROUP 4
#define GRP_SZ  8
#define SCALE   2.5f
#define SH_I    1024
#define MAXMB   96
#define KTW     2048            // words per (128 x 16k) A-fragment tile
#define RS      20              // raw B row stride (words), conflict-free

// R11 validated operating point: 4-stage ring, BK=16
#define STAGES  4
#define STW     4608            // stage words: A 2048 + B 2560
#define SMEM_BYTES (STAGES * STW * 4)   // 73728

#define RT_SMEM (1024 * 33 * 4)         // router transposed-weight smem

// ---------------- scratch ----------------------------------------------------
__device__ uint32_t g_Xsh [(size_t)16 * 64 * KTW];     // shared X A-frags (tf32)
__device__ uint32_t g_Xrt [(size_t)MAXMB * 64 * KTW];  // routed gathered X A-frags
__device__ uint32_t g_Hf  [(size_t)MAXMB * 32 * KTW];  // routed hidden A-frags
__device__ uint32_t g_Hsf [(size_t)16 * 64 * KTW];     // shared hidden A-frags

__device__ int   g_counts[N_EXP];
__device__ int   g_tok[N_EXP * T_TOK];
__device__ float g_wt[N_EXP * T_TOK];
__device__ int   g_nmb;
__device__ int   g_sched_e[MAXMB];
__device__ int   g_sched_m[MAXMB];

// ---------------- helpers ----------------------------------------------------
__device__ __forceinline__ uint32_t f2tf(float x) {
    uint32_t r; asm("cvt.rna.tf32.f32 %0, %1;" : "=r"(r) : "f"(x)); return r;
}
__device__ __forceinline__ uint32_t w2tf(uint32_t w) { return f2tf(__uint_as_float(w)); }
__device__ __forceinline__ void mma8(float* c, const uint32_t* a, uint32_t b0, uint32_t b1) {
    asm volatile("mma.sync.aligned.m16n8k8.row.col.f32.tf32.tf32.f32 "
        "{%0,%1,%2,%3}, {%4,%5,%6,%7}, {%8,%9}, {%0,%1,%2,%3};\n"
        : "+f"(c[0]), "+f"(c[1]), "+f"(c[2]), "+f"(c[3])
        : "r"(a[0]), "r"(a[1]), "r"(a[2]), "r"(a[3]), "r"(b0), "r"(b1));
}
__device__ __forceinline__ uint32_t smem_u32(const void* p) {
    uint32_t a;
    asm("{ .reg .u64 t; cvta.to.shared.u64 t, %1; cvt.u32.u64 %0, t; }" : "=r"(a) : "l"(p));
    return a;
}
__device__ __forceinline__ void cpa16(uint32_t dst, const void* src) {
    asm volatile("cp.async.cg.shared.global [%0], [%1], 16;" :: "r"(dst), "l"(src));
}
#define CPA_COMMIT() asm volatile("cp.async.commit_group;" ::: "memory")
#define CPA_WAIT2()  asm volatile("cp.async.wait_group 2;"  ::: "memory")
#define CPA_WAIT0()  asm volatile("cp.async.wait_group 0;"  ::: "memory")

// fragment addressing (validated R4-R14)
__device__ __forceinline__ int fragA_word(int r, int k) {
    int lt = r >> 4, lg = r & 7, lh = (r >> 3) & 1;
    int ks = k >> 3, k4 = (k >> 2) & 1, kl = k & 3;
    int x = (lg & 3) ^ (ks << 1);
    return lt * 256 + ks * 128 + lg * 16 + ((kl ^ x) << 2) + lh + 2 * k4;
}
__device__ __forceinline__ uint4 ldA_frag(const uint32_t* buf, int t, int ks, int gid, int tig) {
    int x = (gid & 3) ^ (ks << 1);
    return *(const uint4*)&buf[t * 256 + ks * 128 + gid * 16 + ((tig ^ x) << 2)];
}

// ---------------------------------------------------------------------------
// Router. R15 fix: weight staging with MLP=8 batched prefetch (was a serial
// LDG->STS chain, ~64x DRAM latency exposed). Compute phase unchanged.
__global__ __launch_bounds__(512)
void router_kernel(const float* __restrict__ hs,
                   const float* __restrict__ rw,
                   const float* __restrict__ rb) {
    extern __shared__ float sWT[];   // [1024][33]
    int tid = threadIdx.x;
    #pragma unroll
    for (int base = 0; base < N_EXP * H_DIM; base += 512 * 8) {
        float v[8];
        #pragma unroll
        for (int j = 0; j < 8; j++) v[j] = rw[base + j * 512 + tid];
        #pragma unroll
        for (int j = 0; j < 8; j++) {
            int i = base + j * 512 + tid;
            sWT[(i & 1023) * 33 + (i >> 10)] = v[j];
        }
    }
    __syncthreads();

    int warp = tid >> 5, lane = tid & 31;
    int t = blockIdx.x * 16 + warp;
    const float* x = hs + (size_t)t * H_DIM;

    float a0 = 0.f, a1 = 0.f, a2 = 0.f, a3 = 0.f;
    #pragma unroll 4
    for (int h = 0; h < H_DIM; h += 4) {
        float4 xv = *(const float4*)(x + h);
        a0 = fmaf(xv.x, sWT[(h + 0) * 33 + lane], a0);
        a1 = fmaf(xv.y, sWT[(h + 1) * 33 + lane], a1);
        a2 = fmaf(xv.z, sWT[(h + 2) * 33 + lane], a2);
        a3 = fmaf(xv.w, sWT[(h + 3) * 33 + lane], a3);
    }
    float logit = (a0 + a1) + (a2 + a3);
    float score = 1.f / (1.f + expf(-logit));
    float sfc   = score + rb[lane];

    float s[N_EXP], sc[N_EXP];
    #pragma unroll
    for (int e = 0; e < N_EXP; e++) {
        s[e]  = __shfl_sync(0xffffffffu, sfc, e);
        sc[e] = __shfl_sync(0xffffffffu, score, e);
    }

    if (lane == 0) {
        float gsc[N_GROUP];
        #pragma unroll
        for (int g = 0; g < N_GROUP; g++) {
            float m1 = -1e30f, m2 = -1e30f;
            #pragma unroll
            for (int j = 0; j < GRP_SZ; j++) {
                float v = s[g * GRP_SZ + j];
                if (v > m1) { m2 = m1; m1 = v; }
                else if (v > m2) { m2 = v; }
            }
            gsc[g] = m1 + m2;
        }
        int g1 = 0;
        #pragma unroll
        for (int g = 1; g < N_GROUP; g++) if (gsc[g] > gsc[g1]) g1 = g;
        int g2 = -1;
        #pragma unroll
        for (int g = 0; g < N_GROUP; g++) {
            if (g == g1) continue;
            if (g2 < 0 || gsc[g] > gsc[g2]) g2 = g;
        }
        float v[N_EXP];
        #pragma unroll
        for (int e = 0; e < N_EXP; e++) {
            int g = e / GRP_SZ;
            v[e] = (g == g1 || g == g2) ? s[e] : -1e30f;
        }
        int   idx[TOP_K];
        float wsum = 0.f;
        #pragma unroll
        for (int k = 0; k < TOP_K; k++) {
            int b = 0;
            #pragma unroll
            for (int e = 1; e < N_EXP; e++) if (v[e] > v[b]) b = e;
            idx[k] = b;
            v[b] = -2e30f;
            wsum += sc[b];
        }
        float inv = SCALE / (wsum + 1e-20f);
        #pragma unroll
        for (int k = 0; k < TOP_K; k++) {
            int e = idx[k];
            int p = atomicAdd(&g_counts[e], 1);
            g_tok[e * T_TOK + p] = t;
            g_wt [e * T_TOK + p] = sc[e] * inv;
        }
    }
}

__global__ void sched_kernel() {
    int lane = threadIdx.x;
    int cnt = (lane < N_EXP) ? g_counts[lane] : 0;
    int nb = (cnt + 127) >> 7;
    int incl = nb;
    #pragma unroll
    for (int off = 1; off < 32; off <<= 1) {
        int v = __shfl_up_sync(0xffffffffu, incl, off);
        if (lane >= off) incl += v;
    }
    int base = incl - nb;
    for (int j = 0; j < nb; j++) {
        g_sched_e[base + j] = lane;
        g_sched_m[base + j] = j * 128;
    }
    if (lane == 31) g_nmb = incl;
}

// ---------------------------------------------------------------------------
// A-side prep (tf32 + fragment relayout; X reused 8-16x downstream).
__device__ __forceinline__ void prepA_rowtile(uint32_t* dst, const float* src,
                                              int r, int h8, int kt0, int nkt) {
    for (int kt = kt0; kt < kt0 + nkt; kt++) {
        const float* s = src + kt * 16 + h8;
        float4 v0 = *(const float4*)s, v1 = *(const float4*)(s + 4);
        uint32_t* d = dst + (size_t)kt * KTW;
        float f[8] = {v0.x, v0.y, v0.z, v0.w, v1.x, v1.y, v1.z, v1.w};
        #pragma unroll
        for (int i = 0; i < 8; i++) d[fragA_word(r, h8 + i)] = f2tf(f[i]);
    }
}
__global__ void prep_Xsh(const float* __restrict__ X) {
    int bid = blockIdx.x, ktg = blockIdx.y;
    int r = threadIdx.x >> 1, h8 = (threadIdx.x & 1) * 8;
    prepA_rowtile(g_Xsh + (size_t)bid * 64 * KTW,
                  X + (size_t)(bid * 128 + r) * H_DIM, r, h8, ktg * 8, 8);
}
__global__ void prep_Xrt(const float* __restrict__ X) {
    int mb = blockIdx.x, ktg = blockIdx.y;
    if (mb >= g_nmb) return;
    int e = g_sched_e[mb], m0 = g_sched_m[mb], cnt = g_counts[e];
    int r = threadIdx.x >> 1, h8 = (threadIdx.x & 1) * 8;
    int ar = m0 + r; if (ar >= cnt) ar = cnt - 1;
    int tok = g_tok[e * T_TOK + ar];
    prepA_rowtile(g_Xrt + (size_t)mb * 64 * KTW,
                  X + (size_t)tok * H_DIM, r, h8, ktg * 8, 8);
}

// ---------------------------------------------------------------------------
// gateup (R11 body): CTA 128 rows x 64 i-cols, G/U interleaved B rows.
// 8 warps (2m x 4n), warp 64x32, 4-stage BK=16 ring. mode: 0=shared, 1=routed.
__global__ __launch_bounds__(256, 2)
void gateup_k(int mode,
              const float* __restrict__ GW, const float* __restrict__ UW,
              const float* __restrict__ SGW, const float* __restrict__ SUW) {
    extern __shared__ uint32_t dsm[];
    uint32_t sb = smem_u32(dsm);
    int bid = blockIdx.x;

    const uint32_t* Ag;
    const float *gRowBase, *uRowBase;
    uint32_t* Hdst;
    int rows_valid, ktbase;
    if (mode == 0) {
        int mt = bid >> 4, i64 = bid & 15;
        Ag = g_Xsh + (size_t)mt * 64 * KTW;
        gRowBase = SGW + (size_t)(i64 * 64) * H_DIM;
        uRowBase = SUW + (size_t)(i64 * 64) * H_DIM;
        Hdst = g_Hsf + (size_t)mt * 64 * KTW;
        rows_valid = 128; ktbase = i64 * 4;
    } else {
        int mb = bid >> 3;
        if (mb >= g_nmb) return;
        int e = g_sched_e[mb], m0 = g_sched_m[mb], cnt = g_counts[e];
        int i64 = bid & 7;
        Ag = g_Xrt + (size_t)mb * 64 * KTW;
        gRowBase = GW + ((size_t)e * I_DIM + i64 * 64) * H_DIM;
        uRowBase = UW + ((size_t)e * I_DIM + i64 * 64) * H_DIM;
        Hdst = g_Hf + (size_t)mb * 32 * KTW;
        rows_valid = min(128, cnt - m0); ktbase = i64 * 4;
    }

    int tid = threadIdx.x, lane = tid & 31, wid = tid >> 5;
    int gid = lane >> 2, tig = lane & 3;
    int wm = (wid & 1) * 64;
    int wn = (wid >> 1) * 32;

    // B loader: smem row bc <- G/U weight row per 8-row interleave
    int bc = tid >> 1, bh = (tid & 1) * 8;
    int grp = bc >> 4, wi = bc & 15;
    const float* bRow = ((wi >= 8) ? uRowBase : gRowBase)
                        + (size_t)(grp * 8 + (wi & 7)) * H_DIM + bh;

    auto copy_stage = [&](int st, int j) {
        uint32_t dA = sb + (uint32_t)(st * STW + tid * 8) * 4;
        const uint32_t* sA = Ag + (size_t)j * KTW + tid * 8;
        cpa16(dA, sA); cpa16(dA + 16, sA + 4);
        uint32_t dB = sb + (uint32_t)(st * STW + 2048 + bc * RS + bh) * 4;
        const float* sB = bRow + j * 16;
        cpa16(dB, sB); cpa16(dB + 16, sB + 4);
    };

    copy_stage(0, 0); CPA_COMMIT();
    copy_stage(1, 1); CPA_COMMIT();
    copy_stage(2, 2); CPA_COMMIT();

    float acc[4][4][4] = {{{0}}};

    const int NIT = H_DIM / 16;   // 64
    for (int it = 0; it < NIT; it++) {
        CPA_WAIT2();
        __syncthreads();
        int st = it & 3;
        const uint32_t* As = dsm + st * STW;
        const uint32_t* Bs = dsm + st * STW + 2048;

        uint32_t a[4][2][4];
        #pragma unroll
        for (int mt = 0; mt < 4; mt++) {
            int t = (wid & 1) * 4 + mt;
            #pragma unroll
            for (int ks = 0; ks < 2; ks++) {
                uint4 av = ldA_frag(As, t, ks, gid, tig);
                a[mt][ks][0] = av.x; a[mt][ks][1] = av.y;
                a[mt][ks][2] = av.z; a[mt][ks][3] = av.w;
            }
        }
        #pragma unroll
        for (int nt = 0; nt < 4; nt++) {
            int c = wn + nt * 8 + gid;
            #pragma unroll
            for (int ks = 0; ks < 2; ks++) {
                int cb = c * RS + ks * 8 + tig;
                uint32_t b0 = w2tf(Bs[cb]), b1 = w2tf(Bs[cb + 4]);
                #pragma unroll
                for (int mt = 0; mt < 4; mt++)
                    mma8(acc[mt][nt], a[mt][ks], b0, b1);
            }
        }
        if (it + 3 < NIT) copy_stage((it + 3) & 3, it + 3);
        CPA_COMMIT();
    }
    CPA_WAIT0();

    // warp-local epilogue: nt pairs (0,1),(2,3) = (G,U) on same i-cols
    #pragma unroll
    for (int mt = 0; mt < 4; mt++) {
        #pragma unroll
        for (int half = 0; half < 2; half++) {
            int r = wm + mt * 16 + gid + half * 8;
            if (r >= rows_valid) continue;
            #pragma unroll
            for (int p = 0; p < 2; p++) {
                int icol0 = (wn >> 1) + p * 8 + 2 * tig;
                #pragma unroll
                for (int j = 0; j < 2; j++) {
                    float g = acc[mt][2 * p    ][half * 2 + j];
                    float u = acc[mt][2 * p + 1][half * 2 + j];
                    float h = (g / (1.f + expf(-g))) * u;
                    int icol = icol0 + j;
                    Hdst[(size_t)(ktbase + (icol >> 4)) * KTW + fragA_word(r, icol & 15)] = f2tf(h);
                }
            }
        }
    }
}

// ---------------------------------------------------------------------------
// down (R11 body): CTA 128 x 128, 8 warps (2m x 4n), warp 64x32, 4-stage ring.
__global__ __launch_bounds__(256, 2)
void down_k(int mode, const float* __restrict__ DW, const float* __restrict__ SDW,
            float* __restrict__ out) {
    extern __shared__ uint32_t dsm[];
    uint32_t sb = smem_u32(dsm);
    int bid = blockIdx.x;

    const uint32_t* Ag;
    const float* bRowBase;
    int NIT, n0, cnt = 0, m0 = 0, e = 0, bK;
    if (mode == 0) {
        int mt = bid >> 3, nt = bid & 7;
        Ag = g_Hsf + (size_t)mt * 64 * KTW;
        bRowBase = SDW + (size_t)(nt * 128) * SH_I;
        NIT = 64; n0 = nt * 128; m0 = mt * 128; bK = SH_I;
    } else {
        int mb = bid >> 3;
        if (mb >= g_nmb) return;
        e = g_sched_e[mb]; m0 = g_sched_m[mb]; cnt = g_counts[e];
        int nt = bid & 7;
        Ag = g_Hf + (size_t)mb * 32 * KTW;
        bRowBase = DW + ((size_t)e * H_DIM + nt * 128) * I_DIM;
        NIT = 32; n0 = nt * 128; bK = I_DIM;
    }

    int tid = threadIdx.x, lane = tid & 31, wid = tid >> 5;
    int gid = lane >> 2, tig = lane & 3;
    int wm = (wid & 1) * 64;
    int wn = (wid >> 1) * 32;

    int bc = tid >> 1, bh = (tid & 1) * 8;
    const float* bRow = bRowBase + (size_t)bc * bK + bh;

    auto copy_stage = [&](int st, int j) {
        uint32_t dA = sb + (uint32_t)(st * STW + tid * 8) * 4;
        const uint32_t* sA = Ag + (size_t)j * KTW + tid * 8;
        cpa16(dA, sA); cpa16(dA + 16, sA + 4);
        uint32_t dB = sb + (uint32_t)(st * STW + 2048 + bc * RS + bh) * 4;
        const float* sB = bRow + j * 16;
        cpa16(dB, sB); cpa16(dB + 16, sB + 4);
    };

    copy_stage(0, 0); CPA_COMMIT();
    copy_stage(1, 1); CPA_COMMIT();
    copy_stage(2, 2); CPA_COMMIT();

    float acc[4][4][4] = {{{0}}};

    for (int it = 0; it < NIT; it++) {
        CPA_WAIT2();
        __syncthreads();
        int st = it & 3;
        const uint32_t* As = dsm + st * STW;
        const uint32_t* Bs = dsm + st * STW + 2048;

        uint32_t a[4][2][4];
        #pragma unroll
        for (int mt = 0; mt < 4; mt++) {
            int t = (wid & 1) * 4 + mt;
            #pragma unroll
            for (int ks = 0; ks < 2; ks++) {
                uint4 av = ldA_frag(As, t, ks, gid, tig);
                a[mt][ks][0] = av.x; a[mt][ks][1] = av.y;
                a[mt][ks][2] = av.z; a[mt][ks][3] = av.w;
            }
        }
        #pragma unroll
        for (int nt = 0; nt < 4; nt++) {
            int c = wn + nt * 8 + gid;
            #pragma unroll
            for (int ks = 0; ks < 2; ks++) {
                int cb = c * RS + ks * 8 + tig;
                uint32_t b0 = w2tf(Bs[cb]), b1 = w2tf(Bs[cb + 4]);
                #pragma unroll
                for (int mt = 0; mt < 4; mt++)
                    mma8(acc[mt][nt], a[mt][ks], b0, b1);
            }
        }
        if (it + 3 < NIT) copy_stage((it + 3) & 3, it + 3);
        CPA_COMMIT();
    }
    CPA_WAIT0();

    #pragma unroll
    for (int mt = 0; mt < 4; mt++) {
        #pragma unroll
        for (int half = 0; half < 2; half++) {
            int r = wm + mt * 16 + gid + half * 8;
            float wt = 1.f;
            float* op;
            if (mode == 1) {
                if (m0 + r >= cnt) continue;
                int tok = g_tok[e * T_TOK + m0 + r];
                wt = g_wt[e * T_TOK + m0 + r];
                op = out + (size_t)tok * H_DIM;
            } else {
                op = out + (size_t)(m0 + r) * H_DIM;
            }
            #pragma unroll
            for (int nt = 0; nt < 4; nt++) {
                int cb = n0 + wn + nt * 8 + 2 * tig;
                atomicAdd(&op[cb],     acc[mt][nt][half * 2]     * wt);
                atomicAdd(&op[cb + 1], acc[mt][nt][half * 2 + 1] * wt);
            }
        }
    }
}

// ---------------------------------------------------------------------------
extern "C" void kernel_launch(void* const* d_in, const int* in_sizes, int n_in,
                              void* d_out, int out_size) {
    const float* hs  = (const float*)d_in[0];
    const float* rw  = (const float*)d_in[1];
    const float* rb  = (const float*)d_in[2];
    const float* gw  = (const float*)d_in[3];
    const float* uw  = (const float*)d_in[4];
    const float* dw  = (const float*)d_in[5];
    const float* sgw = (const float*)d_in[6];
    const float* suw = (const float*)d_in[7];
    const float* sdw = (const float*)d_in[8];
    float* out = (float*)d_out;

    cudaFuncSetAttribute(router_kernel, cudaFuncAttributeMaxDynamicSharedMemorySize, RT_SMEM);
    cudaFuncSetAttribute(gateup_k, cudaFuncAttributeMaxDynamicSharedMemorySize, SMEM_BYTES);
    cudaFuncSetAttribute(down_k,   cudaFuncAttributeMaxDynamicSharedMemorySize, SMEM_BYTES);

    // one-time side stream + fork/join events (same DAG every call)
    static cudaStream_t s2 = nullptr;
    static cudaEvent_t eFork = nullptr, eJoin = nullptr;
    if (!s2) {
        cudaStreamCreateWithFlags(&s2, cudaStreamNonBlocking);
        cudaEventCreateWithFlags(&eFork, cudaEventDisableTiming);
        cudaEventCreateWithFlags(&eJoin, cudaEventDisableTiming);
    }

    void* cnt_ptr = nullptr;
    cudaGetSymbolAddress(&cnt_ptr, g_counts);
    cudaMemsetAsync(cnt_ptr, 0, N_EXP * sizeof(int));
    cudaMemsetAsync(out, 0, (size_t)T_TOK * H_DIM * sizeof(float));

    // fork: shared-expert path on s2 (independent of router)
    cudaEventRecord(eFork, 0);
    cudaStreamWaitEvent(s2, eFork, 0);
    prep_Xsh<<<dim3(16, 8), 256, 0, s2>>>(hs);
    gateup_k<<<256, 256, SMEM_BYTES, s2>>>(0, gw, uw, sgw, suw);
    down_k  <<<128, 256, SMEM_BYTES, s2>>>(0, dw, sdw, out);
    cudaEventRecord(eJoin, s2);

    // routed path on the main (capture) stream
    router_kernel<<<T_TOK / 16, 512, RT_SMEM>>>(hs, rw, rb);
    sched_kernel<<<1, 32>>>();
    prep_Xrt<<<dim3(MAXMB, 8), 256>>>(hs);
    gateup_k<<<8 * MAXMB, 256, SMEM_BYTES>>>(1, gw, uw, sgw, suw);
    down_k  <<<8 * MAXMB, 256, SMEM_BYTES>>>(1, dw, sdw, out);

    // join
    cudaStreamWaitEvent(0, eJoin, 0);
}

// round 16
// speedup vs baseline: 1.7118x; 1.0314x over previous
#include <cuda_runtime.h>
#include <cuda_bf16.h>
#include <math.h>
#include <stdint.h>

#define T_TOK   2048
#define H_DIM   1024
#define I_DIM   512
#define N_EXP   32
#define TOP_K   4
#define N_GROUP 4
#define GRP_SZ  8
#define SCALE   2.5f
#define SH_I    1024
#define MAXMB   96
#define KTW     2048            // words per (128 x 16k) fragment tile
#define RS      20              // raw B row stride (words), conflict-free

#define STAGES  4
#define STW     4608            // stage words (raw-B variant): A 2048 + B 2560
#define STW_F   4096            // stage words (frag-B variant): A 2048 + B 2048
#define SMEM_BYTES (STAGES * STW * 4)   // 73728 (max of both variants)

#define RT_SMEM (1024 * 33 * 4)

// ---------------- scratch ----------------------------------------------------
__device__ uint32_t g_Xsh [(size_t)16 * 64 * KTW];
__device__ uint32_t g_Xrt [(size_t)MAXMB * 64 * KTW];
__device__ uint32_t g_Hf  [(size_t)MAXMB * 32 * KTW];
__device__ uint32_t g_Hsf [(size_t)16 * 64 * KTW];
__device__ uint32_t g_SGUf[(size_t)16 * 64 * KTW];     // shared gate|up B-frags
__device__ uint32_t g_SDf [(size_t)8 * 64 * KTW];      // shared down B-frags

__device__ int   g_counts[N_EXP];
__device__ int   g_tok[N_EXP * T_TOK];
__device__ float g_wt[N_EXP * T_TOK];
__device__ int   g_nmb;
__device__ int   g_sched_e[MAXMB];
__device__ int   g_sched_m[MAXMB];

// ---------------- helpers ----------------------------------------------------
__device__ __forceinline__ uint32_t f2tf(float x) {
    uint32_t r; asm("cvt.rna.tf32.f32 %0, %1;" : "=r"(r) : "f"(x)); return r;
}
__device__ __forceinline__ uint32_t w2tf(uint32_t w) { return f2tf(__uint_as_float(w)); }
__device__ __forceinline__ void mma8(float* c, const uint32_t* a, uint32_t b0, uint32_t b1) {
    asm volatile("mma.sync.aligned.m16n8k8.row.col.f32.tf32.tf32.f32 "
        "{%0,%1,%2,%3}, {%4,%5,%6,%7}, {%8,%9}, {%0,%1,%2,%3};\n"
        : "+f"(c[0]), "+f"(c[1]), "+f"(c[2]), "+f"(c[3])
        : "r"(a[0]), "r"(a[1]), "r"(a[2]), "r"(a[3]), "r"(b0), "r"(b1));
}
__device__ __forceinline__ uint32_t smem_u32(const void* p) {
    uint32_t a;
    asm("{ .reg .u64 t; cvta.to.shared.u64 t, %1; cvt.u32.u64 %0, t; }" : "=r"(a) : "l"(p));
    return a;
}
__device__ __forceinline__ void cpa16(uint32_t dst, const void* src) {
    asm volatile("cp.async.cg.shared.global [%0], [%1], 16;" :: "r"(dst), "l"(src));
}
#define CPA_COMMIT() asm volatile("cp.async.commit_group;" ::: "memory")
#define CPA_WAIT2()  asm volatile("cp.async.wait_group 2;"  ::: "memory")
#define CPA_WAIT0()  asm volatile("cp.async.wait_group 0;"  ::: "memory")

// fragment addressing (A validated R4-R15, B validated R8)
__device__ __forceinline__ int fragA_word(int r, int k) {
    int lt = r >> 4, lg = r & 7, lh = (r >> 3) & 1;
    int ks = k >> 3, k4 = (k >> 2) & 1, kl = k & 3;
    int x = (lg & 3) ^ (ks << 1);
    return lt * 256 + ks * 128 + lg * 16 + ((kl ^ x) << 2) + lh + 2 * k4;
}
__device__ __forceinline__ int fragB_word(int c, int k) {
    int ks = k >> 3, k4 = (k >> 2) & 1, kl = k & 3;
    int x = (c & 3) ^ (((c >> 3) & 1) << 1);
    return c * 16 + ((kl ^ x) << 2) + k4 + 2 * ks;
}
__device__ __forceinline__ uint4 ldA_frag(const uint32_t* buf, int t, int ks, int gid, int tig) {
    int x = (gid & 3) ^ (ks << 1);
    return *(const uint4*)&buf[t * 256 + ks * 128 + gid * 16 + ((tig ^ x) << 2)];
}
__device__ __forceinline__ uint4 ldB_frag(const uint32_t* buf, int c, int tig) {
    int x = (c & 3) ^ (((c >> 3) & 1) << 1);
    return *(const uint4*)&buf[c * 16 + ((tig ^ x) << 2)];
}

// ---------------------------------------------------------------------------
// Router (validated R15).
__global__ __launch_bounds__(512)
void router_kernel(const float* __restrict__ hs,
                   const float* __restrict__ rw,
                   const float* __restrict__ rb) {
    extern __shared__ float sWT[];
    int tid = threadIdx.x;
    #pragma unroll
    for (int base = 0; base < N_EXP * H_DIM; base += 512 * 8) {
        float v[8];
        #pragma unroll
        for (int j = 0; j < 8; j++) v[j] = rw[base + j * 512 + tid];
        #pragma unroll
        for (int j = 0; j < 8; j++) {
            int i = base + j * 512 + tid;
            sWT[(i & 1023) * 33 + (i >> 10)] = v[j];
        }
    }
    __syncthreads();

    int warp = tid >> 5, lane = tid & 31;
    int t = blockIdx.x * 16 + warp;
    const float* x = hs + (size_t)t * H_DIM;

    float a0 = 0.f, a1 = 0.f, a2 = 0.f, a3 = 0.f;
    #pragma unroll 4
    for (int h = 0; h < H_DIM; h += 4) {
        float4 xv = *(const float4*)(x + h);
        a0 = fmaf(xv.x, sWT[(h + 0) * 33 + lane], a0);
        a1 = fmaf(xv.y, sWT[(h + 1) * 33 + lane], a1);
        a2 = fmaf(xv.z, sWT[(h + 2) * 33 + lane], a2);
        a3 = fmaf(xv.w, sWT[(h + 3) * 33 + lane], a3);
    }
    float logit = (a0 + a1) + (a2 + a3);
    float score = 1.f / (1.f + expf(-logit));
    float sfc   = score + rb[lane];

    float s[N_EXP], sc[N_EXP];
    #pragma unroll
    for (int e = 0; e < N_EXP; e++) {
        s[e]  = __shfl_sync(0xffffffffu, sfc, e);
        sc[e] = __shfl_sync(0xffffffffu, score, e);
    }

    if (lane == 0) {
        float gsc[N_GROUP];
        #pragma unroll
        for (int g = 0; g < N_GROUP; g++) {
            float m1 = -1e30f, m2 = -1e30f;
            #pragma unroll
            for (int j = 0; j < GRP_SZ; j++) {
                float v = s[g * GRP_SZ + j];
                if (v > m1) { m2 = m1; m1 = v; }
                else if (v > m2) { m2 = v; }
            }
            gsc[g] = m1 + m2;
        }
        int g1 = 0;
        #pragma unroll
        for (int g = 1; g < N_GROUP; g++) if (gsc[g] > gsc[g1]) g1 = g;
        int g2 = -1;
        #pragma unroll
        for (int g = 0; g < N_GROUP; g++) {
            if (g == g1) continue;
            if (g2 < 0 || gsc[g] > gsc[g2]) g2 = g;
        }
        float v[N_EXP];
        #pragma unroll
        for (int e = 0; e < N_EXP; e++) {
            int g = e / GRP_SZ;
            v[e] = (g == g1 || g == g2) ? s[e] : -1e30f;
        }
        int   idx[TOP_K];
        float wsum = 0.f;
        #pragma unroll
        for (int k = 0; k < TOP_K; k++) {
            int b = 0;
            #pragma unroll
            for (int e = 1; e < N_EXP; e++) if (v[e] > v[b]) b = e;
            idx[k] = b;
            v[b] = -2e30f;
            wsum += sc[b];
        }
        float inv = SCALE / (wsum + 1e-20f);
        #pragma unroll
        for (int k = 0; k < TOP_K; k++) {
            int e = idx[k];
            int p = atomicAdd(&g_counts[e], 1);
            g_tok[e * T_TOK + p] = t;
            g_wt [e * T_TOK + p] = sc[e] * inv;
        }
    }
}

__global__ void sched_kernel() {
    int lane = threadIdx.x;
    int cnt = (lane < N_EXP) ? g_counts[lane] : 0;
    int nb = (cnt + 127) >> 7;
    int incl = nb;
    #pragma unroll
    for (int off = 1; off < 32; off <<= 1) {
        int v = __shfl_up_sync(0xffffffffu, incl, off);
        if (lane >= off) incl += v;
    }
    int base = incl - nb;
    for (int j = 0; j < nb; j++) {
        g_sched_e[base + j] = lane;
        g_sched_m[base + j] = j * 128;
    }
    if (lane == 31) g_nmb = incl;
}

// ---------------------------------------------------------------------------
// Prep kernels.
__device__ __forceinline__ void prepA_rowtile(uint32_t* dst, const float* src,
                                              int r, int h8, int kt0, int nkt) {
    for (int kt = kt0; kt < kt0 + nkt; kt++) {
        const float* s = src + kt * 16 + h8;
        float4 v0 = *(const float4*)s, v1 = *(const float4*)(s + 4);
        uint32_t* d = dst + (size_t)kt * KTW;
        float f[8] = {v0.x, v0.y, v0.z, v0.w, v1.x, v1.y, v1.z, v1.w};
        #pragma unroll
        for (int i = 0; i < 8; i++) d[fragA_word(r, h8 + i)] = f2tf(f[i]);
    }
}
__device__ __forceinline__ void prepB_rowtile(uint32_t* dst, const float* src,
                                              int c, int h8, int kt0, int nkt) {
    for (int kt = kt0; kt < kt0 + nkt; kt++) {
        const float* s = src + kt * 16 + h8;
        float4 v0 = *(const float4*)s, v1 = *(const float4*)(s + 4);
        uint32_t* d = dst + (size_t)kt * KTW;
        float f[8] = {v0.x, v0.y, v0.z, v0.w, v1.x, v1.y, v1.z, v1.w};
        #pragma unroll
        for (int i = 0; i < 8; i++) d[fragB_word(c, h8 + i)] = f2tf(f[i]);
    }
}
__global__ void prep_Xsh(const float* __restrict__ X) {
    int bid = blockIdx.x, ktg = blockIdx.y;
    int r = threadIdx.x >> 1, h8 = (threadIdx.x & 1) * 8;
    prepA_rowtile(g_Xsh + (size_t)bid * 64 * KTW,
                  X + (size_t)(bid * 128 + r) * H_DIM, r, h8, ktg * 8, 8);
}
__global__ void prep_Xrt(const float* __restrict__ X) {
    int mb = blockIdx.x, ktg = blockIdx.y;
    if (mb >= g_nmb) return;
    int e = g_sched_e[mb], m0 = g_sched_m[mb], cnt = g_counts[e];
    int r = threadIdx.x >> 1, h8 = (threadIdx.x & 1) * 8;
    int ar = m0 + r; if (ar >= cnt) ar = cnt - 1;
    int tok = g_tok[e * T_TOK + ar];
    prepA_rowtile(g_Xrt + (size_t)mb * 64 * KTW,
                  X + (size_t)tok * H_DIM, r, h8, ktg * 8, 8);
}
// Shared gate|up weights -> B frags (col c: grp=c>>4, wi=c&15; G if wi<8 else U)
__global__ void prep_SGU(const float* __restrict__ SGW, const float* __restrict__ SUW) {
    int i64 = blockIdx.x, ktg = blockIdx.y;
    int c = threadIdx.x >> 1, h8 = (threadIdx.x & 1) * 8;
    int grp = c >> 4, wi = c & 15;
    const float* src = ((wi >= 8) ? SUW : SGW)
                       + (size_t)(i64 * 64 + grp * 8 + (wi & 7)) * H_DIM;
    prepB_rowtile(g_SGUf + (size_t)i64 * 64 * KTW, src, c, h8, ktg * 8, 8);
}
__global__ void prep_SD(const float* __restrict__ SDW) {
    int nt = blockIdx.x, ktg = blockIdx.y;
    int c = threadIdx.x >> 1, h8 = (threadIdx.x & 1) * 8;
    prepB_rowtile(g_SDf + (size_t)nt * 64 * KTW,
                  SDW + (size_t)(nt * 128 + c) * SH_I, c, h8, ktg * 8, 8);
}

// ---------------------------------------------------------------------------
// Shared-path GEMM: both A and B in fragment layout (pure LDS.128 + mma).
// CTA 128x128, 8 warps (2m x 4n), warp 64x32, 4-stage BK=16 ring.
// GATEUP=1: silu epilogue into g_Hsf; GATEUP=0: atomicAdd into out.
template <int GATEUP>
__device__ __forceinline__ void shared_body(const uint32_t* Ag, const uint32_t* Bg,
                                            uint32_t* Hdst, float* out,
                                            int m0, int n0, int ktbase, int NIT) {
    extern __shared__ uint32_t dsm[];
    uint32_t sb = smem_u32(dsm);

    int tid = threadIdx.x, lane = tid & 31, wid = tid >> 5;
    int gid = lane >> 2, tig = lane & 3;
    int wm = (wid & 1) * 64;
    int wn = (wid >> 1) * 32;

    auto copy_stage = [&](int st, int j) {
        uint32_t dA = sb + (uint32_t)(st * STW_F + tid * 8) * 4;
        const uint32_t* sA = Ag + (size_t)j * KTW + tid * 8;
        cpa16(dA, sA); cpa16(dA + 16, sA + 4);
        uint32_t dB = sb + (uint32_t)(st * STW_F + 2048 + tid * 8) * 4;
        const uint32_t* sB = Bg + (size_t)j * KTW + tid * 8;
        cpa16(dB, sB); cpa16(dB + 16, sB + 4);
    };

    copy_stage(0, 0); CPA_COMMIT();
    copy_stage(1, 1); CPA_COMMIT();
    copy_stage(2, 2); CPA_COMMIT();

    float acc[4][4][4] = {{{0}}};

    for (int it = 0; it < NIT; it++) {
        CPA_WAIT2();
        __syncthreads();
        int st = it & 3;
        const uint32_t* As = dsm + st * STW_F;
        const uint32_t* Bs = dsm + st * STW_F + 2048;

        uint32_t a[4][2][4];
        #pragma unroll
        for (int mt = 0; mt < 4; mt++) {
            int t = (wid & 1) * 4 + mt;
            #pragma unroll
            for (int ks = 0; ks < 2; ks++) {
                uint4 av = ldA_frag(As, t, ks, gid, tig);
                a[mt][ks][0] = av.x; a[mt][ks][1] = av.y;
                a[mt][ks][2] = av.z; a[mt][ks][3] = av.w;
            }
        }
        #pragma unroll
        for (int nt = 0; nt < 4; nt++) {
            int c = wn + nt * 8 + gid;
            uint4 bv = ldB_frag(Bs, c, tig);
            #pragma unroll
            for (int mt = 0; mt < 4; mt++) {
                mma8(acc[mt][nt], a[mt][0], bv.x, bv.y);
                mma8(acc[mt][nt], a[mt][1], bv.z, bv.w);
            }
        }
        if (it + 3 < NIT) copy_stage((it + 3) & 3, it + 3);
        CPA_COMMIT();
    }
    CPA_WAIT0();

    if (GATEUP) {
        #pragma unroll
        for (int mt = 0; mt < 4; mt++)
            #pragma unroll
            for (int half = 0; half < 2; half++) {
                int r = wm + mt * 16 + gid + half * 8;
                #pragma unroll
                for (int p = 0; p < 2; p++) {
                    int icol0 = (wn >> 1) + p * 8 + 2 * tig;
                    #pragma unroll
                    for (int j = 0; j < 2; j++) {
                        float g = acc[mt][2 * p    ][half * 2 + j];
                        float u = acc[mt][2 * p + 1][half * 2 + j];
                        float h = (g / (1.f + expf(-g))) * u;
                        int icol = icol0 + j;
                        Hdst[(size_t)(ktbase + (icol >> 4)) * KTW + fragA_word(r, icol & 15)] = f2tf(h);
                    }
                }
            }
    } else {
        #pragma unroll
        for (int mt = 0; mt < 4; mt++)
            #pragma unroll
            for (int half = 0; half < 2; half++) {
                int r = wm + mt * 16 + gid + half * 8;
                float* op = out + (size_t)(m0 + r) * H_DIM;
                #pragma unroll
                for (int nt = 0; nt < 4; nt++) {
                    int cb = n0 + wn + nt * 8 + 2 * tig;
                    atomicAdd(&op[cb],     acc[mt][nt][half * 2]);
                    atomicAdd(&op[cb + 1], acc[mt][nt][half * 2 + 1]);
                }
            }
    }
}

__global__ __launch_bounds__(256, 2)
void gateup_sh() {
    int mt = blockIdx.x >> 4, i64 = blockIdx.x & 15;
    shared_body<1>(g_Xsh + (size_t)mt * 64 * KTW,
                   g_SGUf + (size_t)i64 * 64 * KTW,
                   g_Hsf + (size_t)mt * 64 * KTW, nullptr,
                   0, 0, i64 * 4, H_DIM / 16);
}
__global__ __launch_bounds__(256, 2)
void down_sh(float* __restrict__ out) {
    int mt = blockIdx.x >> 3, nt = blockIdx.x & 7;
    shared_body<0>(g_Hsf + (size_t)mt * 64 * KTW,
                   g_SDf + (size_t)nt * 64 * KTW,
                   nullptr, out, mt * 128, nt * 128, 0, SH_I / 16);
}

// ---------------------------------------------------------------------------
// Routed gateup (R11 body, raw B + cvt at consume).
__global__ __launch_bounds__(256, 2)
void gateup_rt(const float* __restrict__ GW, const float* __restrict__ UW) {
    extern __shared__ uint32_t dsm[];
    uint32_t sb = smem_u32(dsm);
    int bid = blockIdx.x;
    int mb = bid >> 3;
    if (mb >= g_nmb) return;
    int e = g_sched_e[mb], m0 = g_sched_m[mb], cnt = g_counts[e];
    int i64 = bid & 7;
    const uint32_t* Ag = g_Xrt + (size_t)mb * 64 * KTW;
    const float* gRowBase = GW + ((size_t)e * I_DIM + i64 * 64) * H_DIM;
    const float* uRowBase = UW + ((size_t)e * I_DIM + i64 * 64) * H_DIM;
    uint32_t* Hdst = g_Hf + (size_t)mb * 32 * KTW;
    int rows_valid = min(128, cnt - m0), ktbase = i64 * 4;

    int tid = threadIdx.x, lane = tid & 31, wid = tid >> 5;
    int gid = lane >> 2, tig = lane & 3;
    int wm = (wid & 1) * 64;
    int wn = (wid >> 1) * 32;

    int bc = tid >> 1, bh = (tid & 1) * 8;
    int grp = bc >> 4, wi = bc & 15;
    const float* bRow = ((wi >= 8) ? uRowBase : gRowBase)
                        + (size_t)(grp * 8 + (wi & 7)) * H_DIM + bh;

    auto copy_stage = [&](int st, int j) {
        uint32_t dA = sb + (uint32_t)(st * STW + tid * 8) * 4;
        const uint32_t* sA = Ag + (size_t)j * KTW + tid * 8;
        cpa16(dA, sA); cpa16(dA + 16, sA + 4);
        uint32_t dB = sb + (uint32_t)(st * STW + 2048 + bc * RS + bh) * 4;
        const float* sB = bRow + j * 16;
        cpa16(dB, sB); cpa16(dB + 16, sB + 4);
    };

    copy_stage(0, 0); CPA_COMMIT();
    copy_stage(1, 1); CPA_COMMIT();
    copy_stage(2, 2); CPA_COMMIT();

    float acc[4][4][4] = {{{0}}};

    const int NIT = H_DIM / 16;
    for (int it = 0; it < NIT; it++) {
        CPA_WAIT2();
        __syncthreads();
        int st = it & 3;
        const uint32_t* As = dsm + st * STW;
        const uint32_t* Bs = dsm + st * STW + 2048;

        uint32_t a[4][2][4];
        #pragma unroll
        for (int mt = 0; mt < 4; mt++) {
            int t = (wid & 1) * 4 + mt;
            #pragma unroll
            for (int ks = 0; ks < 2; ks++) {
                uint4 av = ldA_frag(As, t, ks, gid, tig);
                a[mt][ks][0] = av.x; a[mt][ks][1] = av.y;
                a[mt][ks][2] = av.z; a[mt][ks][3] = av.w;
            }
        }
        #pragma unroll
        for (int nt = 0; nt < 4; nt++) {
            int c = wn + nt * 8 + gid;
            #pragma unroll
            for (int ks = 0; ks < 2; ks++) {
                int cb = c * RS + ks * 8 + tig;
                uint32_t b0 = w2tf(Bs[cb]), b1 = w2tf(Bs[cb + 4]);
                #pragma unroll
                for (int mt = 0; mt < 4; mt++)
                    mma8(acc[mt][nt], a[mt][ks], b0, b1);
            }
        }
        if (it + 3 < NIT) copy_stage((it + 3) & 3, it + 3);
        CPA_COMMIT();
    }
    CPA_WAIT0();

    #pragma unroll
    for (int mt = 0; mt < 4; mt++)
        #pragma unroll
        for (int half = 0; half < 2; half++) {
            int r = wm + mt * 16 + gid + half * 8;
            if (r >= rows_valid) continue;
            #pragma unroll
            for (int p = 0; p < 2; p++) {
                int icol0 = (wn >> 1) + p * 8 + 2 * tig;
                #pragma unroll
                for (int j = 0; j < 2; j++) {
                    float g = acc[mt][2 * p    ][half * 2 + j];
                    float u = acc[mt][2 * p + 1][half * 2 + j];
                    float h = (g / (1.f + expf(-g))) * u;
                    int icol = icol0 + j;
                    Hdst[(size_t)(ktbase + (icol >> 4)) * KTW + fragA_word(r, icol & 15)] = f2tf(h);
                }
            }
        }
}

// Routed down (R11 body).
__global__ __launch_bounds__(256, 2)
void down_rt(const float* __restrict__ DW, float* __restrict__ out) {
    extern __shared__ uint32_t dsm[];
    uint32_t sb = smem_u32(dsm);
    int bid = blockIdx.x;
    int mb = bid >> 3;
    if (mb >= g_nmb) return;
    int e = g_sched_e[mb], m0 = g_sched_m[mb], cnt = g_counts[e];
    int nt = bid & 7;
    const uint32_t* Ag = g_Hf + (size_t)mb * 32 * KTW;
    const float* bRowBase = DW + ((size_t)e * H_DIM + nt * 128) * I_DIM;
    int NIT = I_DIM / 16, n0 = nt * 128;

    int tid = threadIdx.x, lane = tid & 31, wid = tid >> 5;
    int gid = lane >> 2, tig = lane & 3;
    int wm = (wid & 1) * 64;
    int wn = (wid >> 1) * 32;

    int bc = tid >> 1, bh = (tid & 1) * 8;
    const float* bRow = bRowBase + (size_t)bc * I_DIM + bh;

    auto copy_stage = [&](int st, int j) {
        uint32_t dA = sb + (uint32_t)(st * STW + tid * 8) * 4;
        const uint32_t* sA = Ag + (size_t)j * KTW + tid * 8;
        cpa16(dA, sA); cpa16(dA + 16, sA + 4);
        uint32_t dB = sb + (uint32_t)(st * STW + 2048 + bc * RS + bh) * 4;
        const float* sB = bRow + j * 16;
        cpa16(dB, sB); cpa16(dB + 16, sB + 4);
    };

    copy_stage(0, 0); CPA_COMMIT();
    copy_stage(1, 1); CPA_COMMIT();
    copy_stage(2, 2); CPA_COMMIT();

    float acc[4][4][4] = {{{0}}};

    for (int it = 0; it < NIT; it++) {
        CPA_WAIT2();
        __syncthreads();
        int st = it & 3;
        const uint32_t* As = dsm + st * STW;
        const uint32_t* Bs = dsm + st * STW + 2048;

        uint32_t a[4][2][4];
        #pragma unroll
        for (int mt = 0; mt < 4; mt++) {
            int t = (wid & 1) * 4 + mt;
            #pragma unroll
            for (int ks = 0; ks < 2; ks++) {
                uint4 av = ldA_frag(As, t, ks, gid, tig);
                a[mt][ks][0] = av.x; a[mt][ks][1] = av.y;
                a[mt][ks][2] = av.z; a[mt][ks][3] = av.w;
            }
        }
        #pragma unroll
        for (int nt2 = 0; nt2 < 4; nt2++) {
            int c = wn + nt2 * 8 + gid;
            #pragma unroll
            for (int ks = 0; ks < 2; ks++) {
                int cb = c * RS + ks * 8 + tig;
                uint32_t b0 = w2tf(Bs[cb]), b1 = w2tf(Bs[cb + 4]);
                #pragma unroll
                for (int mt = 0; mt < 4; mt++)
                    mma8(acc[mt][nt2], a[mt][ks], b0, b1);
            }
        }
        if (it + 3 < NIT) copy_stage((it + 3) & 3, it + 3);
        CPA_COMMIT();
    }
    CPA_WAIT0();

    #pragma unroll
    for (int mt = 0; mt < 4; mt++)
        #pragma unroll
        for (int half = 0; half < 2; half++) {
            int r = wm + mt * 16 + gid + half * 8;
            if (m0 + r >= cnt) continue;
            int tok = g_tok[e * T_TOK + m0 + r];
            float wt = g_wt[e * T_TOK + m0 + r];
            float* op = out + (size_t)tok * H_DIM;
            #pragma unroll
            for (int nt2 = 0; nt2 < 4; nt2++) {
                int cb = n0 + wn + nt2 * 8 + 2 * tig;
                atomicAdd(&op[cb],     acc[mt][nt2][half * 2]     * wt);
                atomicAdd(&op[cb + 1], acc[mt][nt2][half * 2 + 1] * wt);
            }
        }
}

// ---------------------------------------------------------------------------
extern "C" void kernel_launch(void* const* d_in, const int* in_sizes, int n_in,
                              void* d_out, int out_size) {
    const float* hs  = (const float*)d_in[0];
    const float* rw  = (const float*)d_in[1];
    const float* rb  = (const float*)d_in[2];
    const float* gw  = (const float*)d_in[3];
    const float* uw  = (const float*)d_in[4];
    const float* dw  = (const float*)d_in[5];
    const float* sgw = (const float*)d_in[6];
    const float* suw = (const float*)d_in[7];
    const float* sdw = (const float*)d_in[8];
    float* out = (float*)d_out;

    cudaFuncSetAttribute(router_kernel, cudaFuncAttributeMaxDynamicSharedMemorySize, RT_SMEM);
    cudaFuncSetAttribute(gateup_sh, cudaFuncAttributeMaxDynamicSharedMemorySize, SMEM_BYTES);
    cudaFuncSetAttribute(down_sh,   cudaFuncAttributeMaxDynamicSharedMemorySize, SMEM_BYTES);
    cudaFuncSetAttribute(gateup_rt, cudaFuncAttributeMaxDynamicSharedMemorySize, SMEM_BYTES);
    cudaFuncSetAttribute(down_rt,   cudaFuncAttributeMaxDynamicSharedMemorySize, SMEM_BYTES);

    // one-time LOW-priority side stream (shared path yields SMs to routed path)
    static cudaStream_t s2 = nullptr;
    static cudaEvent_t eFork = nullptr, eJoin = nullptr;
    if (!s2) {
        int leastP = 0, greatestP = 0;
        cudaDeviceGetStreamPriorityRange(&leastP, &greatestP);
        cudaStreamCreateWithPriority(&s2, cudaStreamNonBlocking, leastP);
        cudaEventCreateWithFlags(&eFork, cudaEventDisableTiming);
        cudaEventCreateWithFlags(&eJoin, cudaEventDisableTiming);
    }

    void* cnt_ptr = nullptr;
    cudaGetSymbolAddress(&cnt_ptr, g_counts);
    cudaMemsetAsync(cnt_ptr, 0, N_EXP * sizeof(int));
    cudaMemsetAsync(out, 0, (size_t)T_TOK * H_DIM * sizeof(float));

    // fork: shared-expert path on s2
    cudaEventRecord(eFork, 0);
    cudaStreamWaitEvent(s2, eFork, 0);
    prep_Xsh<<<dim3(16, 8), 256, 0, s2>>>(hs);
    prep_SGU<<<dim3(16, 8), 256, 0, s2>>>(sgw, suw);
    prep_SD <<<dim3(8, 8),  256, 0, s2>>>(sdw);
    gateup_sh<<<256, 256, SMEM_BYTES, s2>>>();
    down_sh  <<<128, 256, SMEM_BYTES, s2>>>(out);
    cudaEventRecord(eJoin, s2);

    // routed path on the main (capture) stream
    router_kernel<<<T_TOK / 16, 512, RT_SMEM>>>(hs, rw, rb);
    sched_kernel<<<1, 32>>>();
    prep_Xrt<<<dim3(MAXMB, 8), 256>>>(hs);
    gateup_rt<<<8 * MAXMB, 256, SMEM_BYTES>>>(gw, uw);
    down_rt  <<<8 * MAXMB, 256, SMEM_BYTES>>>(dw, out);

    // join
    cudaStreamWaitEvent(0, eJoin, 0);
}

// round 17
// speedup vs baseline: 2.4424x; 1.4268x over previous
#include <cuda_runtime.h>
#include <cuda_bf16.h>
#include <cuda_fp16.h>
#include <math.h>
#include <stdint.h>

#define T_TOK   2048
#define H_DIM   1024
#define I_DIM   512
#define N_EXP   32
#define TOP_K   4
#define N_GROUP 4
#define GRP_SZ  8
#define SCALE   2.5f
#define SH_I    1024
#define MAXMB   96
#define KTWH    1024            // words per f16 (128 x 16k) fragment tile (A or B)
#define RSW     40              // raw f32 B row stride (words): conflict-free f16-pair LDS.64

#define STAGES  4
#define STW_F   2048            // frag-B stage: A 1024 + B 1024 words (8 KB)
#define STW_R   6144            // raw-B stage: A 1024 + B 5120 words (24 KB)
#define SMEM_F  (STAGES * STW_F * 4)   // 32768
#define SMEM_R  (STAGES * STW_R * 4)   // 98304

#define RT_SMEM (1024 * 33 * 4)

// ---------------- scratch (f16 fragment tiles) -------------------------------
__device__ uint32_t g_Xsh [(size_t)16 * 64 * KTWH];
__device__ uint32_t g_Xrt [(size_t)MAXMB * 64 * KTWH];
__device__ uint32_t g_Hf  [(size_t)MAXMB * 32 * KTWH];
__device__ uint32_t g_Hsf [(size_t)16 * 64 * KTWH];
__device__ uint32_t g_SGUf[(size_t)16 * 64 * KTWH];
__device__ uint32_t g_SDf [(size_t)8 * 64 * KTWH];

__device__ int   g_counts[N_EXP];
__device__ int   g_tok[N_EXP * T_TOK];
__device__ float g_wt[N_EXP * T_TOK];
__device__ int   g_nmb;
__device__ int   g_sched_e[MAXMB];
__device__ int   g_sched_m[MAXMB];

// ---------------- helpers ----------------------------------------------------
__device__ __forceinline__ uint32_t pk(float lo, float hi) {
    uint32_t d; asm("cvt.rn.f16x2.f32 %0, %1, %2;" : "=r"(d) : "f"(hi), "f"(lo)); return d;
}
__device__ __forceinline__ void mma16(float* c, const uint32_t* a, uint32_t b0, uint32_t b1) {
    asm volatile("mma.sync.aligned.m16n8k16.row.col.f32.f16.f16.f32 "
        "{%0,%1,%2,%3}, {%4,%5,%6,%7}, {%8,%9}, {%0,%1,%2,%3};\n"
        : "+f"(c[0]), "+f"(c[1]), "+f"(c[2]), "+f"(c[3])
        : "r"(a[0]), "r"(a[1]), "r"(a[2]), "r"(a[3]), "r"(b0), "r"(b1));
}
__device__ __forceinline__ uint32_t smem_u32(const void* p) {
    uint32_t a;
    asm("{ .reg .u64 t; cvta.to.shared.u64 t, %1; cvt.u32.u64 %0, t; }" : "=r"(a) : "l"(p));
    return a;
}
__device__ __forceinline__ void cpa16(uint32_t dst, const void* src) {
    asm volatile("cp.async.cg.shared.global [%0], [%1], 16;" :: "r"(dst), "l"(src));
}
#define CPA_COMMIT() asm volatile("cp.async.commit_group;" ::: "memory")
#define CPA_WAIT2()  asm volatile("cp.async.wait_group 2;"  ::: "memory")
#define CPA_WAIT0()  asm volatile("cp.async.wait_group 0;"  ::: "memory")

// f16 fragment addressing.
// A tile (128 rows x 16 k): word = t*128 + g*16 + ((kp&3 ^ (g&3))<<2) + hh + 2*(kp>>2)
//   r = t*16 + hh*8 + g; kp = k>>1 (f16x2 pair, lo=even k).
// Reader: LDS.128 at (t, g=gid, q=tig^(gid&3)) -> {a0,a1,a2,a3} of m16n8k16.
__device__ __forceinline__ int fragAh_word(int r, int kp) {
    int t = r >> 4, g = r & 7, hh = (r >> 3) & 1;
    return t * 128 + g * 16 + (((kp & 3) ^ (g & 3)) << 2) + hh + 2 * (kp >> 2);
}
// B tile (128 cols x 16 k): word = c*8 + ((kp&3 ^ x)<<1) + (kp>>2), x = (c&3)^(((c>>3)&1)<<1)
// Reader: LDS.64 at (c, q=tig^x) -> {b0 (kp=tig), b1 (kp=tig+4)}.
__device__ __forceinline__ int fragBh_word(int c, int kp) {
    int x = (c & 3) ^ (((c >> 3) & 1) << 1);
    return c * 8 + ((((kp & 3)) ^ x) << 1) + (kp >> 2);
}
__device__ __forceinline__ uint4 ldAh(const uint32_t* buf, int t, int gid, int tig) {
    int x = gid & 3;
    return *(const uint4*)&buf[t * 128 + gid * 16 + ((tig ^ x) << 2)];
}
__device__ __forceinline__ uint2 ldBh(const uint32_t* buf, int c, int tig) {
    int x = (c & 3) ^ (((c >> 3) & 1) << 1);
    return *(const uint2*)&buf[c * 8 + ((tig ^ x) << 1)];
}

// ---------------------------------------------------------------------------
// Router (validated R15).
__global__ __launch_bounds__(512)
void router_kernel(const float* __restrict__ hs,
                   const float* __restrict__ rw,
                   const float* __restrict__ rb) {
    extern __shared__ float sWT[];
    int tid = threadIdx.x;
    #pragma unroll
    for (int base = 0; base < N_EXP * H_DIM; base += 512 * 8) {
        float v[8];
        #pragma unroll
        for (int j = 0; j < 8; j++) v[j] = rw[base + j * 512 + tid];
        #pragma unroll
        for (int j = 0; j < 8; j++) {
            int i = base + j * 512 + tid;
            sWT[(i & 1023) * 33 + (i >> 10)] = v[j];
        }
    }
    __syncthreads();

    int warp = tid >> 5, lane = tid & 31;
    int t = blockIdx.x * 16 + warp;
    const float* x = hs + (size_t)t * H_DIM;

    float a0 = 0.f, a1 = 0.f, a2 = 0.f, a3 = 0.f;
    #pragma unroll 4
    for (int h = 0; h < H_DIM; h += 4) {
        float4 xv = *(const float4*)(x + h);
        a0 = fmaf(xv.x, sWT[(h + 0) * 33 + lane], a0);
        a1 = fmaf(xv.y, sWT[(h + 1) * 33 + lane], a1);
        a2 = fmaf(xv.z, sWT[(h + 2) * 33 + lane], a2);
        a3 = fmaf(xv.w, sWT[(h + 3) * 33 + lane], a3);
    }
    float logit = (a0 + a1) + (a2 + a3);
    float score = 1.f / (1.f + expf(-logit));
    float sfc   = score + rb[lane];

    float s[N_EXP], sc[N_EXP];
    #pragma unroll
    for (int e = 0; e < N_EXP; e++) {
        s[e]  = __shfl_sync(0xffffffffu, sfc, e);
        sc[e] = __shfl_sync(0xffffffffu, score, e);
    }

    if (lane == 0) {
        float gsc[N_GROUP];
        #pragma unroll
        for (int g = 0; g < N_GROUP; g++) {
            float m1 = -1e30f, m2 = -1e30f;
            #pragma unroll
            for (int j = 0; j < GRP_SZ; j++) {
                float v = s[g * GRP_SZ + j];
                if (v > m1) { m2 = m1; m1 = v; }
                else if (v > m2) { m2 = v; }
            }
            gsc[g] = m1 + m2;
        }
        int g1 = 0;
        #pragma unroll
        for (int g = 1; g < N_GROUP; g++) if (gsc[g] > gsc[g1]) g1 = g;
        int g2 = -1;
        #pragma unroll
        for (int g = 0; g < N_GROUP; g++) {
            if (g == g1) continue;
            if (g2 < 0 || gsc[g] > gsc[g2]) g2 = g;
        }
        float v[N_EXP];
        #pragma unroll
        for (int e = 0; e < N_EXP; e++) {
            int g = e / GRP_SZ;
            v[e] = (g == g1 || g == g2) ? s[e] : -1e30f;
        }
        int   idx[TOP_K];
        float wsum = 0.f;
        #pragma unroll
        for (int k = 0; k < TOP_K; k++) {
            int b = 0;
            #pragma unroll
            for (int e = 1; e < N_EXP; e++) if (v[e] > v[b]) b = e;
            idx[k] = b;
            v[b] = -2e30f;
            wsum += sc[b];
        }
        float inv = SCALE / (wsum + 1e-20f);
        #pragma unroll
        for (int k = 0; k < TOP_K; k++) {
            int e = idx[k];
            int p = atomicAdd(&g_counts[e], 1);
            g_tok[e * T_TOK + p] = t;
            g_wt [e * T_TOK + p] = sc[e] * inv;
        }
    }
}

__global__ void sched_kernel() {
    int lane = threadIdx.x;
    int cnt = (lane < N_EXP) ? g_counts[lane] : 0;
    int nb = (cnt + 127) >> 7;
    int incl = nb;
    #pragma unroll
    for (int off = 1; off < 32; off <<= 1) {
        int v = __shfl_up_sync(0xffffffffu, incl, off);
        if (lane >= off) incl += v;
    }
    int base = incl - nb;
    for (int j = 0; j < nb; j++) {
        g_sched_e[base + j] = lane;
        g_sched_m[base + j] = j * 128;
    }
    if (lane == 31) g_nmb = incl;
}

// ---------------------------------------------------------------------------
// Prep: f32 -> f16 fragment tiles.
__device__ __forceinline__ void prepAh_rowtile(uint32_t* dst, const float* src,
                                               int r, int h8, int kt0, int nkt) {
    for (int kt = kt0; kt < kt0 + nkt; kt++) {
        const float* s = src + kt * 16 + h8;
        float4 v0 = *(const float4*)s, v1 = *(const float4*)(s + 4);
        float f[8] = {v0.x, v0.y, v0.z, v0.w, v1.x, v1.y, v1.z, v1.w};
        uint32_t* d = dst + (size_t)kt * KTWH;
        #pragma unroll
        for (int j = 0; j < 4; j++) {
            int kp = (h8 >> 1) + j;
            d[fragAh_word(r, kp)] = pk(f[2 * j], f[2 * j + 1]);
        }
    }
}
__device__ __forceinline__ void prepBh_rowtile(uint32_t* dst, const float* src,
                                               int c, int h8, int kt0, int nkt) {
    for (int kt = kt0; kt < kt0 + nkt; kt++) {
        const float* s = src + kt * 16 + h8;
        float4 v0 = *(const float4*)s, v1 = *(const float4*)(s + 4);
        float f[8] = {v0.x, v0.y, v0.z, v0.w, v1.x, v1.y, v1.z, v1.w};
        uint32_t* d = dst + (size_t)kt * KTWH;
        #pragma unroll
        for (int j = 0; j < 4; j++) {
            int kp = (h8 >> 1) + j;
            d[fragBh_word(c, kp)] = pk(f[2 * j], f[2 * j + 1]);
        }
    }
}
__global__ void prep_Xsh(const float* __restrict__ X) {
    int bid = blockIdx.x, ktg = blockIdx.y;
    int r = threadIdx.x >> 1, h8 = (threadIdx.x & 1) * 8;
    prepAh_rowtile(g_Xsh + (size_t)bid * 64 * KTWH,
                   X + (size_t)(bid * 128 + r) * H_DIM, r, h8, ktg * 8, 8);
}
__global__ void prep_Xrt(const float* __restrict__ X) {
    int mb = blockIdx.x, ktg = blockIdx.y;
    if (mb >= g_nmb) return;
    int e = g_sched_e[mb], m0 = g_sched_m[mb], cnt = g_counts[e];
    int r = threadIdx.x >> 1, h8 = (threadIdx.x & 1) * 8;
    int ar = m0 + r; if (ar >= cnt) ar = cnt - 1;
    int tok = g_tok[e * T_TOK + ar];
    prepAh_rowtile(g_Xrt + (size_t)mb * 64 * KTWH,
                   X + (size_t)tok * H_DIM, r, h8, ktg * 8, 8);
}
__global__ void prep_SGU(const float* __restrict__ SGW, const float* __restrict__ SUW) {
    int i64 = blockIdx.x, ktg = blockIdx.y;
    int c = threadIdx.x >> 1, h8 = (threadIdx.x & 1) * 8;
    int grp = c >> 4, wi = c & 15;
    const float* src = ((wi >= 8) ? SUW : SGW)
                       + (size_t)(i64 * 64 + grp * 8 + (wi & 7)) * H_DIM;
    prepBh_rowtile(g_SGUf + (size_t)i64 * 64 * KTWH, src, c, h8, ktg * 8, 8);
}
__global__ void prep_SD(const float* __restrict__ SDW) {
    int nt = blockIdx.x, ktg = blockIdx.y;
    int c = threadIdx.x >> 1, h8 = (threadIdx.x & 1) * 8;
    prepBh_rowtile(g_SDf + (size_t)nt * 64 * KTWH,
                   SDW + (size_t)(nt * 128 + c) * SH_I, c, h8, ktg * 8, 8);
}

// ---------------------------------------------------------------------------
// Shared-path GEMM: A and B f16 fragment tiles. CTA 128x128, 8 warps (2m x 4n),
// warp 64x32, 4-stage BK=16 ring. GATEUP=1: silu -> g_Hsf; 0: atomicAdd out.
template <int GATEUP>
__device__ __forceinline__ void shared_body(const uint32_t* Ag, const uint32_t* Bg,
                                            uint32_t* Hdst, float* out,
                                            int m0, int n0, int ktbase, int NIT) {
    extern __shared__ uint32_t dsm[];
    uint32_t sb = smem_u32(dsm);

    int tid = threadIdx.x, lane = tid & 31, wid = tid >> 5;
    int gid = lane >> 2, tig = lane & 3;
    int wm = (wid & 1) * 64;
    int wn = (wid >> 1) * 32;

    auto copy_stage = [&](int st, int j) {
        cpa16(sb + (uint32_t)(st * STW_F + tid * 4) * 4,        Ag + (size_t)j * KTWH + tid * 4);
        cpa16(sb + (uint32_t)(st * STW_F + 1024 + tid * 4) * 4, Bg + (size_t)j * KTWH + tid * 4);
    };

    copy_stage(0, 0); CPA_COMMIT();
    copy_stage(1, 1); CPA_COMMIT();
    copy_stage(2, 2); CPA_COMMIT();

    float acc[4][4][4] = {{{0}}};

    for (int it = 0; it < NIT; it++) {
        CPA_WAIT2();
        __syncthreads();
        int st = it & 3;
        const uint32_t* As = dsm + st * STW_F;
        const uint32_t* Bs = dsm + st * STW_F + 1024;

        uint32_t a[4][4];
        #pragma unroll
        for (int mt = 0; mt < 4; mt++) {
            int t = (wid & 1) * 4 + mt;
            uint4 av = ldAh(As, t, gid, tig);
            a[mt][0] = av.x; a[mt][1] = av.y; a[mt][2] = av.z; a[mt][3] = av.w;
        }
        #pragma unroll
        for (int nt = 0; nt < 4; nt++) {
            int c = wn + nt * 8 + gid;
            uint2 bv = ldBh(Bs, c, tig);
            #pragma unroll
            for (int mt = 0; mt < 4; mt++)
                mma16(acc[mt][nt], a[mt], bv.x, bv.y);
        }
        if (it + 3 < NIT) copy_stage((it + 3) & 3, it + 3);
        CPA_COMMIT();
    }
    CPA_WAIT0();

    if (GATEUP) {
        #pragma unroll
        for (int mt = 0; mt < 4; mt++)
            #pragma unroll
            for (int half = 0; half < 2; half++) {
                int r = wm + mt * 16 + gid + half * 8;
                #pragma unroll
                for (int p = 0; p < 2; p++) {
                    int icol0 = (wn >> 1) + p * 8 + 2 * tig;
                    float g0 = acc[mt][2 * p    ][half * 2];
                    float u0 = acc[mt][2 * p + 1][half * 2];
                    float g1 = acc[mt][2 * p    ][half * 2 + 1];
                    float u1 = acc[mt][2 * p + 1][half * 2 + 1];
                    float h0 = (g0 / (1.f + expf(-g0))) * u0;
                    float h1 = (g1 / (1.f + expf(-g1))) * u1;
                    int kt = ktbase + (icol0 >> 4);
                    Hdst[(size_t)kt * KTWH + fragAh_word(r, (icol0 & 15) >> 1)] = pk(h0, h1);
                }
            }
    } else {
        #pragma unroll
        for (int mt = 0; mt < 4; mt++)
            #pragma unroll
            for (int half = 0; half < 2; half++) {
                int r = wm + mt * 16 + gid + half * 8;
                float* op = out + (size_t)(m0 + r) * H_DIM;
                #pragma unroll
                for (int nt = 0; nt < 4; nt++) {
                    int cb = n0 + wn + nt * 8 + 2 * tig;
                    atomicAdd(&op[cb],     acc[mt][nt][half * 2]);
                    atomicAdd(&op[cb + 1], acc[mt][nt][half * 2 + 1]);
                }
            }
    }
}

__global__ __launch_bounds__(256, 2)
void gateup_sh() {
    int mt = blockIdx.x >> 4, i64 = blockIdx.x & 15;
    shared_body<1>(g_Xsh + (size_t)mt * 64 * KTWH,
                   g_SGUf + (size_t)i64 * 64 * KTWH,
                   g_Hsf + (size_t)mt * 64 * KTWH, nullptr,
                   0, 0, i64 * 4, H_DIM / 16);
}
__global__ __launch_bounds__(256, 2)
void down_sh(float* __restrict__ out) {
    int mt = blockIdx.x >> 3, nt = blockIdx.x & 7;
    shared_body<0>(g_Hsf + (size_t)mt * 64 * KTWH,
                   g_SDf + (size_t)nt * 64 * KTWH,
                   nullptr, out, mt * 128, nt * 128, 0, SH_I / 16);
}

// ---------------------------------------------------------------------------
// Routed GEMMs: A = f16 frag tiles, B = raw f32 rows (RSW=40, conflict-free
// pair LDS.64), cvt to f16x2 at consume.
__global__ __launch_bounds__(256, 2)
void gateup_rt(const float* __restrict__ GW, const float* __restrict__ UW) {
    extern __shared__ uint32_t dsm[];
    uint32_t sb = smem_u32(dsm);
    int bid = blockIdx.x;
    int mb = bid >> 3;
    if (mb >= g_nmb) return;
    int e = g_sched_e[mb], m0 = g_sched_m[mb], cnt = g_counts[e];
    int i64 = bid & 7;
    const uint32_t* Ag = g_Xrt + (size_t)mb * 64 * KTWH;
    const float* gRowBase = GW + ((size_t)e * I_DIM + i64 * 64) * H_DIM;
    const float* uRowBase = UW + ((size_t)e * I_DIM + i64 * 64) * H_DIM;
    uint32_t* Hdst = g_Hf + (size_t)mb * 32 * KTWH;
    int rows_valid = min(128, cnt - m0), ktbase = i64 * 4;

    int tid = threadIdx.x, lane = tid & 31, wid = tid >> 5;
    int gid = lane >> 2, tig = lane & 3;
    int wm = (wid & 1) * 64;
    int wn = (wid >> 1) * 32;

    int bc = tid >> 1, bh = (tid & 1) * 8;
    int grp = bc >> 4, wi = bc & 15;
    const float* bRow = ((wi >= 8) ? uRowBase : gRowBase)
                        + (size_t)(grp * 8 + (wi & 7)) * H_DIM + bh;

    auto copy_stage = [&](int st, int j) {
        cpa16(sb + (uint32_t)(st * STW_R + tid * 4) * 4, Ag + (size_t)j * KTWH + tid * 4);
        uint32_t dB = sb + (uint32_t)(st * STW_R + 1024 + bc * RSW + bh) * 4;
        const float* sB = bRow + j * 16;
        cpa16(dB, sB); cpa16(dB + 16, sB + 4);
    };

    copy_stage(0, 0); CPA_COMMIT();
    copy_stage(1, 1); CPA_COMMIT();
    copy_stage(2, 2); CPA_COMMIT();

    float acc[4][4][4] = {{{0}}};

    const int NIT = H_DIM / 16;
    for (int it = 0; it < NIT; it++) {
        CPA_WAIT2();
        __syncthreads();
        int st = it & 3;
        const uint32_t* As = dsm + st * STW_R;
        const float* BsF = (const float*)(dsm + st * STW_R + 1024);

        uint32_t a[4][4];
        #pragma unroll
        for (int mt = 0; mt < 4; mt++) {
            int t = (wid & 1) * 4 + mt;
            uint4 av = ldAh(As, t, gid, tig);
            a[mt][0] = av.x; a[mt][1] = av.y; a[mt][2] = av.z; a[mt][3] = av.w;
        }
        #pragma unroll
        for (int nt = 0; nt < 4; nt++) {
            int c = wn + nt * 8 + gid;
            float2 p0 = *(const float2*)&BsF[c * RSW + 2 * tig];
            float2 p1 = *(const float2*)&BsF[c * RSW + 8 + 2 * tig];
            uint32_t b0 = pk(p0.x, p0.y), b1 = pk(p1.x, p1.y);
            #pragma unroll
            for (int mt = 0; mt < 4; mt++)
                mma16(acc[mt][nt], a[mt], b0, b1);
        }
        if (it + 3 < NIT) copy_stage((it + 3) & 3, it + 3);
        CPA_COMMIT();
    }
    CPA_WAIT0();

    #pragma unroll
    for (int mt = 0; mt < 4; mt++)
        #pragma unroll
        for (int half = 0; half < 2; half++) {
            int r = wm + mt * 16 + gid + half * 8;
            if (r >= rows_valid) continue;
            #pragma unroll
            for (int p = 0; p < 2; p++) {
                int icol0 = (wn >> 1) + p * 8 + 2 * tig;
                float g0 = acc[mt][2 * p    ][half * 2];
                float u0 = acc[mt][2 * p + 1][half * 2];
                float g1 = acc[mt][2 * p    ][half * 2 + 1];
                float u1 = acc[mt][2 * p + 1][half * 2 + 1];
                float h0 = (g0 / (1.f + expf(-g0))) * u0;
                float h1 = (g1 / (1.f + expf(-g1))) * u1;
                int kt = ktbase + (icol0 >> 4);
                Hdst[(size_t)kt * KTWH + fragAh_word(r, (icol0 & 15) >> 1)] = pk(h0, h1);
            }
        }
}

__global__ __launch_bounds__(256, 2)
void down_rt(const float* __restrict__ DW, float* __restrict__ out) {
    extern __shared__ uint32_t dsm[];
    uint32_t sb = smem_u32(dsm);
    int bid = blockIdx.x;
    int mb = bid >> 3;
    if (mb >= g_nmb) return;
    int e = g_sched_e[mb], m0 = g_sched_m[mb], cnt = g_counts[e];
    int nt0 = bid & 7;
    const uint32_t* Ag = g_Hf + (size_t)mb * 32 * KTWH;
    const float* bRowBase = DW + ((size_t)e * H_DIM + nt0 * 128) * I_DIM;
    int NIT = I_DIM / 16, n0 = nt0 * 128;

    int tid = threadIdx.x, lane = tid & 31, wid = tid >> 5;
    int gid = lane >> 2, tig = lane & 3;
    int wm = (wid & 1) * 64;
    int wn = (wid >> 1) * 32;

    int bc = tid >> 1, bh = (tid & 1) * 8;
    const float* bRow = bRowBase + (size_t)bc * I_DIM + bh;

    auto copy_stage = [&](int st, int j) {
        cpa16(sb + (uint32_t)(st * STW_R + tid * 4) * 4, Ag + (size_t)j * KTWH + tid * 4);
        uint32_t dB = sb + (uint32_t)(st * STW_R + 1024 + bc * RSW + bh) * 4;
        const float* sB = bRow + j * 16;
        cpa16(dB, sB); cpa16(dB + 16, sB + 4);
    };

    copy_stage(0, 0); CPA_COMMIT();
    copy_stage(1, 1); CPA_COMMIT();
    copy_stage(2, 2); CPA_COMMIT();

    float acc[4][4][4] = {{{0}}};

    for (int it = 0; it < NIT; it++) {
        CPA_WAIT2();
        __syncthreads();
        int st = it & 3;
        const uint32_t* As = dsm + st * STW_R;
        const float* BsF = (const float*)(dsm + st * STW_R + 1024);

        uint32_t a[4][4];
        #pragma unroll
        for (int mt = 0; mt < 4; mt++) {
            int t = (wid & 1) * 4 + mt;
            uint4 av = ldAh(As, t, gid, tig);
            a[mt][0] = av.x; a[mt][1] = av.y; a[mt][2] = av.z; a[mt][3] = av.w;
        }
        #pragma unroll
        for (int nt = 0; nt < 4; nt++) {
            int c = wn + nt * 8 + gid;
            float2 p0 = *(const float2*)&BsF[c * RSW + 2 * tig];
            float2 p1 = *(const float2*)&BsF[c * RSW + 8 + 2 * tig];
            uint32_t b0 = pk(p0.x, p0.y), b1 = pk(p1.x, p1.y);
            #pragma unroll
            for (int mt = 0; mt < 4; mt++)
                mma16(acc[mt][nt], a[mt], b0, b1);
        }
        if (it + 3 < NIT) copy_stage((it + 3) & 3, it + 3);
        CPA_COMMIT();
    }
    CPA_WAIT0();

    #pragma unroll
    for (int mt = 0; mt < 4; mt++)
        #pragma unroll
        for (int half = 0; half < 2; half++) {
            int r = wm + mt * 16 + gid + half * 8;
            if (m0 + r >= cnt) continue;
            int tok = g_tok[e * T_TOK + m0 + r];
            float wt = g_wt[e * T_TOK + m0 + r];
            float* op = out + (size_t)tok * H_DIM;
            #pragma unroll
            for (int nt = 0; nt < 4; nt++) {
                int cb = n0 + wn + nt * 8 + 2 * tig;
                atomicAdd(&op[cb],     acc[mt][nt][half * 2]     * wt);
                atomicAdd(&op[cb + 1], acc[mt][nt][half * 2 + 1] * wt);
            }
        }
}

// ---------------------------------------------------------------------------
extern "C" void kernel_launch(void* const* d_in, const int* in_sizes, int n_in,
                              void* d_out, int out_size) {
    const float* hs  = (const float*)d_in[0];
    const float* rw  = (const float*)d_in[1];
    const float* rb  = (const float*)d_in[2];
    const float* gw  = (const float*)d_in[3];
    const float* uw  = (const float*)d_in[4];
    const float* dw  = (const float*)d_in[5];
    const float* sgw = (const float*)d_in[6];
    const float* suw = (const float*)d_in[7];
    const float* sdw = (const float*)d_in[8];
    float* out = (float*)d_out;

    cudaFuncSetAttribute(router_kernel, cudaFuncAttributeMaxDynamicSharedMemorySize, RT_SMEM);
    cudaFuncSetAttribute(gateup_rt, cudaFuncAttributeMaxDynamicSharedMemorySize, SMEM_R);
    cudaFuncSetAttribute(down_rt,   cudaFuncAttributeMaxDynamicSharedMemorySize, SMEM_R);

    static cudaStream_t s2 = nullptr;
    static cudaEvent_t eFork = nullptr, eJoin = nullptr;
    if (!s2) {
        int leastP = 0, greatestP = 0;
        cudaDeviceGetStreamPriorityRange(&leastP, &greatestP);
        cudaStreamCreateWithPriority(&s2, cudaStreamNonBlocking, leastP);
        cudaEventCreateWithFlags(&eFork, cudaEventDisableTiming);
        cudaEventCreateWithFlags(&eJoin, cudaEventDisableTiming);
    }

    void* cnt_ptr = nullptr;
    cudaGetSymbolAddress(&cnt_ptr, g_counts);
    cudaMemsetAsync(cnt_ptr, 0, N_EXP * sizeof(int));
    cudaMemsetAsync(out, 0, (size_t)T_TOK * H_DIM * sizeof(float));

    // fork: shared-expert path (low priority)
    cudaEventRecord(eFork, 0);
    cudaStreamWaitEvent(s2, eFork, 0);
    prep_Xsh<<<dim3(16, 8), 256, 0, s2>>>(hs);
    prep_SGU<<<dim3(16, 8), 256, 0, s2>>>(sgw, suw);
    prep_SD <<<dim3(8, 8),  256, 0, s2>>>(sdw);
    gateup_sh<<<256, 256, SMEM_F, s2>>>();
    down_sh  <<<128, 256, SMEM_F, s2>>>(out);
    cudaEventRecord(eJoin, s2);

    // routed path (main/capture stream)
    router_kernel<<<T_TOK / 16, 512, RT_SMEM>>>(hs, rw, rb);
    sched_kernel<<<1, 32>>>();
    prep_Xrt<<<dim3(MAXMB, 8), 256>>>(hs);
    gateup_rt<<<8 * MAXMB, 256, SMEM_R>>>(gw, uw);
    down_rt  <<<8 * MAXMB, 256, SMEM_R>>>(dw, out);

    cudaStreamWaitEvent(0, eJoin, 0);
}